// round 1
// baseline (speedup 1.0000x reference)
#include <cuda_runtime.h>
#include <cstdint>
#include <cstddef>

#define B_ 16
#define T_ 512
#define E_ 768
#define H_ 12
#define D_ 64
#define L_ 100
#define MROWS (B_*T_)   // 8192
#define NEGBIG (-1e9f)

// ---------------- scratch (alloc-free rule: __device__ globals) ----------------
__device__ float g_att[MROWS * L_];
__device__ float g_htruth[MROWS * E_];
__device__ float g_hunknown[MROWS * E_];
__device__ float g_q[MROWS * E_];
__device__ float g_k[MROWS * E_];
__device__ float g_v[MROWS * E_];
__device__ float g_ctx[MROWS * E_];
__device__ float g_z[MROWS * E_];

// ---------------- generic tiled SGEMM: C = A @ op(B) (+bias)(+res) ----------------
// A: [M,K] row-major.  TRANSB=false: B is [K,N] row-major.  TRANSB=true: B is [N,K] row-major.
template<bool TRANSB>
__global__ __launch_bounds__(256)
void sgemm_kernel(const float* __restrict__ A, const float* __restrict__ Bm,
                  const float* __restrict__ bias, const float* __restrict__ res,
                  float* __restrict__ C, int M, int N, int K)
{
    __shared__ float As[16][65];
    __shared__ float Bs[16][65];
    const int tid = threadIdx.x;
    const int tx = tid & 15, ty = tid >> 4;
    const int m0 = blockIdx.y * 64, n0 = blockIdx.x * 64;
    float acc[4][4] = {};

    for (int k0 = 0; k0 < K; k0 += 16) {
        {
            int kk = tid & 15, mb = tid >> 4;
            #pragma unroll
            for (int s = 0; s < 4; s++) {
                int mm = mb + s * 16;
                int gm = m0 + mm, gk = k0 + kk;
                As[kk][mm] = (gm < M && gk < K) ? A[(size_t)gm * K + gk] : 0.f;
            }
        }
        if (!TRANSB) {
            int nn = tid & 63, kb = tid >> 6;
            #pragma unroll
            for (int s = 0; s < 4; s++) {
                int kk = kb + s * 4;
                int gn = n0 + nn, gk = k0 + kk;
                Bs[kk][nn] = (gn < N && gk < K) ? Bm[(size_t)gk * N + gn] : 0.f;
            }
        } else {
            int kk = tid & 15, nb = tid >> 4;
            #pragma unroll
            for (int s = 0; s < 4; s++) {
                int nn = nb + s * 16;
                int gn = n0 + nn, gk = k0 + kk;
                Bs[kk][nn] = (gn < N && gk < K) ? Bm[(size_t)gn * K + gk] : 0.f;
            }
        }
        __syncthreads();
        #pragma unroll
        for (int kk = 0; kk < 16; kk++) {
            float a[4], bb[4];
            #pragma unroll
            for (int i = 0; i < 4; i++) a[i] = As[kk][ty * 4 + i];
            #pragma unroll
            for (int j = 0; j < 4; j++) bb[j] = Bs[kk][tx * 4 + j];
            #pragma unroll
            for (int i = 0; i < 4; i++)
                #pragma unroll
                for (int j = 0; j < 4; j++)
                    acc[i][j] += a[i] * bb[j];
        }
        __syncthreads();
    }

    #pragma unroll
    for (int i = 0; i < 4; i++) {
        int gm = m0 + ty * 4 + i;
        if (gm >= M) continue;
        #pragma unroll
        for (int j = 0; j < 4; j++) {
            int gn = n0 + tx * 4 + j;
            if (gn >= N) continue;
            float v = acc[i][j];
            if (bias) v += bias[gn];
            if (res)  v += res[(size_t)gm * N + gn];
            C[(size_t)gm * N + gn] = v;
        }
    }
}

// ---------------- softmax over L=100 (one warp per row) ----------------
__global__ __launch_bounds__(256)
void softmax100_kernel(const float* __restrict__ scores, float* __restrict__ att)
{
    int warp = (blockIdx.x * blockDim.x + threadIdx.x) >> 5;
    int lane = threadIdx.x & 31;
    if (warp >= MROWS) return;
    const float* s = scores + (size_t)warp * L_;
    float v[4];
    float mx = -INFINITY;
    #pragma unroll
    for (int i = 0; i < 4; i++) {
        int l = lane + i * 32;
        v[i] = (l < L_) ? s[l] : -INFINITY;
        mx = fmaxf(mx, v[i]);
    }
    #pragma unroll
    for (int w = 16; w; w >>= 1) mx = fmaxf(mx, __shfl_xor_sync(0xffffffffu, mx, w));
    float sum = 0.f;
    #pragma unroll
    for (int i = 0; i < 4; i++) {
        int l = lane + i * 32;
        v[i] = (l < L_) ? expf(v[i] - mx) : 0.f;
        sum += v[i];
    }
    #pragma unroll
    for (int w = 16; w; w >>= 1) sum += __shfl_xor_sync(0xffffffffu, sum, w);
    float inv = 1.f / sum;
    #pragma unroll
    for (int i = 0; i < 4; i++) {
        int l = lane + i * 32;
        if (l < L_) att[(size_t)warp * L_ + l] = v[i] * inv;
    }
}

// ---------------- h_unknown = X + tp ----------------
__global__ __launch_bounds__(256)
void addtp_kernel(const float* __restrict__ X, const float* __restrict__ tp,
                  float* __restrict__ hu)
{
    size_t i = (size_t)blockIdx.x * blockDim.x + threadIdx.x;
    if (i >= (size_t)MROWS * E_) return;
    hu[i] = X[i] + tp[i % E_];
}

// ---------------- flash attention: per (b, h, 64-query tile) ----------------
#define FSTR 65
extern __shared__ float fsm[];
__global__ __launch_bounds__(256)
void flash_kernel(const float* __restrict__ q, const float* __restrict__ k,
                  const float* __restrict__ v, const float* __restrict__ amask,
                  float* __restrict__ ctx)
{
    const int b = blockIdx.z, h = blockIdx.y, q0 = blockIdx.x * 64;
    const int tid = threadIdx.x;
    const int tx = tid & 15, ty = tid >> 4;
    float* Qs = fsm;
    float* Ks = Qs + 64 * FSTR;
    float* Vs = Ks + 64 * FSTR;
    float* Ps = Vs + 64 * FSTR;

    // load Q tile (pre-scaled by 1/sqrt(D))
    for (int idx = tid; idx < 64 * 64; idx += 256) {
        int r = idx >> 6, d = idx & 63;
        Qs[r * FSTR + d] = q[(((size_t)b * T_ + q0 + r) * H_ + h) * D_ + d] * 0.125f;
    }

    float m_prev[4], l_prev[4], O[4][4] = {};
    #pragma unroll
    for (int i = 0; i < 4; i++) { m_prev[i] = -INFINITY; l_prev[i] = 0.f; }

    for (int kt = 0; kt < T_; kt += 64) {
        for (int idx = tid; idx < 64 * 64; idx += 256) {
            int r = idx >> 6, d = idx & 63;
            size_t base = (((size_t)b * T_ + kt + r) * H_ + h) * D_ + d;
            Ks[r * FSTR + d] = k[base];
            Vs[r * FSTR + d] = v[base];
        }
        __syncthreads();

        float s[4][4] = {};
        #pragma unroll 8
        for (int d = 0; d < 64; d++) {
            float a[4], bb[4];
            #pragma unroll
            for (int i = 0; i < 4; i++) a[i] = Qs[(ty * 4 + i) * FSTR + d];
            #pragma unroll
            for (int j = 0; j < 4; j++) bb[j] = Ks[(tx * 4 + j) * FSTR + d];
            #pragma unroll
            for (int i = 0; i < 4; i++)
                #pragma unroll
                for (int j = 0; j < 4; j++)
                    s[i][j] += a[i] * bb[j];
        }

        // biases: pad mask + diag mask
        #pragma unroll
        for (int j = 0; j < 4; j++) {
            int kg = kt + tx * 4 + j;
            float mbias = (1.f - amask[(size_t)b * T_ + kg]) * NEGBIG;
            #pragma unroll
            for (int i = 0; i < 4; i++) {
                int qg = q0 + ty * 4 + i;
                s[i][j] += mbias + ((qg == kg) ? NEGBIG : 0.f);
            }
        }

        // per-q-row max across 16 lanes (same ty group)
        float mnew[4], corr[4], rsum[4];
        #pragma unroll
        for (int i = 0; i < 4; i++) {
            float rm = fmaxf(fmaxf(s[i][0], s[i][1]), fmaxf(s[i][2], s[i][3]));
            #pragma unroll
            for (int w = 8; w; w >>= 1) rm = fmaxf(rm, __shfl_xor_sync(0xffffffffu, rm, w));
            mnew[i] = fmaxf(m_prev[i], rm);
            corr[i] = __expf(m_prev[i] - mnew[i]);
            float rs = 0.f;
            #pragma unroll
            for (int j = 0; j < 4; j++) {
                float p = __expf(s[i][j] - mnew[i]);
                s[i][j] = p;
                rs += p;
            }
            #pragma unroll
            for (int w = 8; w; w >>= 1) rs += __shfl_xor_sync(0xffffffffu, rs, w);
            rsum[i] = rs;
            l_prev[i] = l_prev[i] * corr[i] + rs;
            m_prev[i] = mnew[i];
            #pragma unroll
            for (int j = 0; j < 4; j++) O[i][j] *= corr[i];
        }
        (void)rsum;

        // write P tile
        #pragma unroll
        for (int i = 0; i < 4; i++)
            #pragma unroll
            for (int j = 0; j < 4; j++)
                Ps[(ty * 4 + i) * FSTR + tx * 4 + j] = s[i][j];
        __syncthreads();

        // O += P @ V
        #pragma unroll 8
        for (int kk = 0; kk < 64; kk++) {
            float p[4], vv[4];
            #pragma unroll
            for (int i = 0; i < 4; i++) p[i] = Ps[(ty * 4 + i) * FSTR + kk];
            #pragma unroll
            for (int j = 0; j < 4; j++) vv[j] = Vs[kk * FSTR + tx * 4 + j];
            #pragma unroll
            for (int i = 0; i < 4; i++)
                #pragma unroll
                for (int j = 0; j < 4; j++)
                    O[i][j] += p[i] * vv[j];
        }
        __syncthreads();
    }

    #pragma unroll
    for (int i = 0; i < 4; i++) {
        float inv = 1.f / l_prev[i];
        int qg = q0 + ty * 4 + i;
        #pragma unroll
        for (int j = 0; j < 4; j++) {
            ctx[(((size_t)b * T_ + qg) * H_ + h) * D_ + tx * 4 + j] = O[i][j] * inv;
        }
    }
}

// ---------------- LayerNorm (two-pass) + final residual ----------------
__global__ __launch_bounds__(256)
void ln_kernel(const float* __restrict__ z, const float* __restrict__ g,
               const float* __restrict__ bb, const float* __restrict__ ht,
               float* __restrict__ out)
{
    const int m = blockIdx.x;
    const int t = threadIdx.x;
    __shared__ float buf[E_];
    __shared__ float red[8];
    const int lane = t & 31, wrp = t >> 5;

    float s = 0.f;
    for (int e = t; e < E_; e += 256) {
        float x = z[(size_t)m * E_ + e];
        buf[e] = x;
        s += x;
    }
    #pragma unroll
    for (int w = 16; w; w >>= 1) s += __shfl_xor_sync(0xffffffffu, s, w);
    if (lane == 0) red[wrp] = s;
    __syncthreads();
    float mu = 0.f;
    #pragma unroll
    for (int i = 0; i < 8; i++) mu += red[i];
    mu *= (1.f / E_);
    __syncthreads();

    float vs = 0.f;
    for (int e = t; e < E_; e += 256) {
        float d = buf[e] - mu;
        vs += d * d;
    }
    #pragma unroll
    for (int w = 16; w; w >>= 1) vs += __shfl_xor_sync(0xffffffffu, vs, w);
    if (lane == 0) red[wrp] = vs;
    __syncthreads();
    float var = 0.f;
    #pragma unroll
    for (int i = 0; i < 8; i++) var += red[i];
    var *= (1.f / E_);
    float rs = rsqrtf(var + 1e-12f);

    for (int e = t; e < E_; e += 256) {
        out[(size_t)m * E_ + e] =
            (buf[e] - mu) * rs * g[e] + bb[e] + ht[(size_t)m * E_ + e];
    }
}

// ---------------- launch ----------------
extern "C" void kernel_launch(void* const* d_in, const int* in_sizes, int n_in,
                              void* d_out, int out_size)
{
    const float* X    = (const float*)d_in[0];
    const float* amsk = (const float*)d_in[1];
    const float* TE   = (const float*)d_in[2];
    const float* tp   = (const float*)d_in[3];
    const float* Wq   = (const float*)d_in[4];
    const float* bq   = (const float*)d_in[5];
    const float* Wk   = (const float*)d_in[6];
    const float* bk   = (const float*)d_in[7];
    const float* Wv   = (const float*)d_in[8];
    const float* bv   = (const float*)d_in[9];
    const float* Wo   = (const float*)d_in[10];
    const float* bo   = (const float*)d_in[11];
    const float* lng  = (const float*)d_in[12];
    const float* lnb  = (const float*)d_in[13];

    float* out    = (float*)d_out;
    float* scores = out + (size_t)MROWS * E_;   // second output tensor

    float *p_att, *p_ht, *p_hu, *p_q, *p_k, *p_v, *p_ctx, *p_z;
    cudaGetSymbolAddress((void**)&p_att, g_att);
    cudaGetSymbolAddress((void**)&p_ht,  g_htruth);
    cudaGetSymbolAddress((void**)&p_hu,  g_hunknown);
    cudaGetSymbolAddress((void**)&p_q,   g_q);
    cudaGetSymbolAddress((void**)&p_k,   g_k);
    cudaGetSymbolAddress((void**)&p_v,   g_v);
    cudaGetSymbolAddress((void**)&p_ctx, g_ctx);
    cudaGetSymbolAddress((void**)&p_z,   g_z);

    const int flash_smem = 4 * 64 * FSTR * sizeof(float);
    cudaFuncSetAttribute(flash_kernel, cudaFuncAttributeMaxDynamicSharedMemorySize,
                         flash_smem);

    dim3 blk(256);

    // 1) scores = X @ TE^T   [8192,100]
    {
        dim3 grid((L_ + 63) / 64, MROWS / 64);
        sgemm_kernel<true><<<grid, blk>>>(X, TE, nullptr, nullptr, scores,
                                          MROWS, L_, E_);
    }
    // 2) att = softmax_L(scores)
    softmax100_kernel<<<MROWS / 8, blk>>>(scores, p_att);

    // 3) h_truth = att @ TE + X
    {
        dim3 grid(E_ / 64, MROWS / 64);
        sgemm_kernel<false><<<grid, blk>>>(p_att, TE, nullptr, X, p_ht,
                                           MROWS, E_, L_);
    }
    // 4) h_unknown = X + tp
    addtp_kernel<<<(MROWS * E_ + 255) / 256, blk>>>(X, tp, p_hu);

    // 5) q/k/v projections
    {
        dim3 grid(E_ / 64, MROWS / 64);
        sgemm_kernel<false><<<grid, blk>>>(p_hu, Wq, bq, nullptr, p_q, MROWS, E_, E_);
        sgemm_kernel<false><<<grid, blk>>>(p_ht, Wk, bk, nullptr, p_k, MROWS, E_, E_);
        sgemm_kernel<false><<<grid, blk>>>(p_ht, Wv, bv, nullptr, p_v, MROWS, E_, E_);
    }
    // 6) flash attention (diag + pad mask)
    {
        dim3 grid(T_ / 64, H_, B_);
        flash_kernel<<<grid, blk, flash_smem>>>(p_q, p_k, p_v, amsk, p_ctx);
    }
    // 7) z = ctx @ Wo + bo + h_unknown
    {
        dim3 grid(E_ / 64, MROWS / 64);
        sgemm_kernel<false><<<grid, blk>>>(p_ctx, Wo, bo, p_hu, p_z, MROWS, E_, E_);
    }
    // 8) out = LN(z) * g + b + h_truth
    ln_kernel<<<MROWS, blk>>>(p_z, lng, lnb, p_ht, out);
}

// round 4
// speedup vs baseline: 1.9305x; 1.9305x over previous
#include <cuda_runtime.h>
#include <cuda_bf16.h>
#include <cstdint>
#include <cstddef>

#define B_ 16
#define T_ 512
#define E_ 768
#define H_ 12
#define D_ 64
#define L_ 100
#define MROWS (B_*T_)   // 8192
#define NEGBIG (-1e9f)
typedef __nv_bfloat16 bf16;

// ---------------- scratch (__device__ globals; alloc-free rule) ----------------
__device__ bf16 g_Xhi[MROWS*E_], g_Xlo[MROWS*E_];
__device__ bf16 g_atthi[MROWS*128], g_attlo[MROWS*128];
__device__ float g_ht[MROWS*E_];
__device__ bf16 g_hthi[MROWS*E_], g_htlo[MROWS*E_];
__device__ float g_q[MROWS*E_], g_k[MROWS*E_], g_v[MROWS*E_];
__device__ bf16 g_ctxhi[MROWS*E_], g_ctxlo[MROWS*E_];
__device__ float g_z[MROWS*E_];
__device__ bf16 g_Wqthi[E_*E_], g_Wqtlo[E_*E_];
__device__ bf16 g_Wkthi[E_*E_], g_Wktlo[E_*E_];
__device__ bf16 g_Wvthi[E_*E_], g_Wvtlo[E_*E_];
__device__ bf16 g_Wothi[E_*E_], g_Wotlo[E_*E_];
__device__ bf16 g_TEhi[128*E_], g_TElo[128*E_];
__device__ bf16 g_TEthi[E_*128], g_TEtlo[E_*128];
__device__ float g_bq2[E_];

// ---------------- helpers ----------------
__device__ __forceinline__ uint32_t smem_u32(const void* p){
    uint32_t a;
    asm("{ .reg .u64 t; cvta.to.shared.u64 t, %1; cvt.u32.u64 %0, t; }":"=r"(a):"l"(p));
    return a;
}
__device__ __forceinline__ void cp16(uint32_t dst, const void* src){
    asm volatile("cp.async.cg.shared.global [%0], [%1], 16;" :: "r"(dst), "l"(src));
}
#define CP_COMMIT() asm volatile("cp.async.commit_group;":::"memory")
#define CP_WAIT1()  asm volatile("cp.async.wait_group 1;":::"memory")
#define CP_WAIT0()  asm volatile("cp.async.wait_group 0;":::"memory")

__device__ __forceinline__ void mma16816(float* c, const uint32_t* a, const uint32_t* b){
    asm volatile(
        "mma.sync.aligned.m16n8k16.row.col.f32.bf16.bf16.f32 "
        "{%0,%1,%2,%3}, {%4,%5,%6,%7}, {%8,%9}, {%0,%1,%2,%3};"
        : "+f"(c[0]), "+f"(c[1]), "+f"(c[2]), "+f"(c[3])
        : "r"(a[0]), "r"(a[1]), "r"(a[2]), "r"(a[3]), "r"(b[0]), "r"(b[1]));
}

#define AST 40   // smem row stride in bf16 (padding: r*20+c distinct banks)

// ---------------- split-bf16 HMMA GEMM: C[M,N] = A @ B^T (+epilogue) ----------------
// A (hi/lo): [M,K] row-major, ld=lda. B (hi/lo): [N,K] row-major, ld=ldb.
// EPI: 0 = scores (store [M,100], guard n<100)
//      1 = +bias, store fp32 [M,768]
//      2 = +Xres, store fp32 C and bf16 split Chi/Clo   (h_truth)
//      3 = +bias +Xres +tp, store fp32                  (z)
template<int EPI>
__global__ __launch_bounds__(256)
void mma_gemm(const bf16* __restrict__ Ahi, const bf16* __restrict__ Alo, int lda,
              const bf16* __restrict__ Bhi, const bf16* __restrict__ Blo, int ldb,
              int K,
              const float* __restrict__ bias, const float* __restrict__ Xres,
              const float* __restrict__ tp,
              float* __restrict__ C,
              bf16* __restrict__ Chi, bf16* __restrict__ Clo)
{
    extern __shared__ bf16 smem[];   // [2 stages][4 mats][128*AST]
    const int tid = threadIdx.x;
    const int lane = tid & 31, wid = tid >> 5;
    const int m0 = blockIdx.y << 7, n0 = blockIdx.x << 7;
    const int wm = wid & 1, wn = wid >> 1;    // warp tile: 64x32
    const int g = lane >> 2, tg = lane & 3;

    float acc[4][4][4] = {};

    const bf16* srcs[4] = {Ahi, Alo, Bhi, Blo};
    const int   lds_[4] = {lda, lda, ldb, ldb};
    const int   r0s_[4] = {m0, m0, n0, n0};

    const int nst = K >> 5;

    // issue cp.async for one k32 stage into buffer st
    auto issue = [&](int st, int k0){
        #pragma unroll
        for (int mat = 0; mat < 4; mat++){
            bf16* dstm = smem + ((st * 4 + mat) * 128 * AST);
            #pragma unroll
            for (int it = 0; it < 2; it++){
                int idx = tid + (it << 8);
                int r = idx >> 2, c = idx & 3;
                cp16(smem_u32(dstm + r * AST + c * 8),
                     srcs[mat] + (size_t)(r0s_[mat] + r) * lds_[mat] + k0 + c * 8);
            }
        }
        CP_COMMIT();
    };

    issue(0, 0);
    if (nst > 1) issue(1, 32);

    for (int s = 0; s < nst; s++){
        if (s + 1 < nst) CP_WAIT1(); else CP_WAIT0();
        __syncthreads();
        const bf16* As_hi = smem + (((s & 1) * 4 + 0) * 128 * AST);
        const bf16* As_lo = smem + (((s & 1) * 4 + 1) * 128 * AST);
        const bf16* Bs_hi = smem + (((s & 1) * 4 + 2) * 128 * AST);
        const bf16* Bs_lo = smem + (((s & 1) * 4 + 3) * 128 * AST);

        #pragma unroll
        for (int kh = 0; kh < 2; kh++){
            const int c0 = (kh << 4) + tg * 2;
            uint32_t bh[4][2], bl[4][2];
            #pragma unroll
            for (int nt = 0; nt < 4; nt++){
                int rn = (wn << 5) + (nt << 3) + g;
                bh[nt][0] = *(const uint32_t*)(Bs_hi + rn * AST + c0);
                bh[nt][1] = *(const uint32_t*)(Bs_hi + rn * AST + c0 + 8);
                bl[nt][0] = *(const uint32_t*)(Bs_lo + rn * AST + c0);
                bl[nt][1] = *(const uint32_t*)(Bs_lo + rn * AST + c0 + 8);
            }
            #pragma unroll
            for (int mt = 0; mt < 4; mt++){
                int ra = (wm << 6) + (mt << 4) + g;
                uint32_t ah[4], al[4];
                ah[0] = *(const uint32_t*)(As_hi + ra * AST + c0);
                ah[1] = *(const uint32_t*)(As_hi + (ra + 8) * AST + c0);
                ah[2] = *(const uint32_t*)(As_hi + ra * AST + c0 + 8);
                ah[3] = *(const uint32_t*)(As_hi + (ra + 8) * AST + c0 + 8);
                al[0] = *(const uint32_t*)(As_lo + ra * AST + c0);
                al[1] = *(const uint32_t*)(As_lo + (ra + 8) * AST + c0);
                al[2] = *(const uint32_t*)(As_lo + ra * AST + c0 + 8);
                al[3] = *(const uint32_t*)(As_lo + (ra + 8) * AST + c0 + 8);
                #pragma unroll
                for (int nt = 0; nt < 4; nt++){
                    mma16816(acc[mt][nt], ah, bh[nt]);
                    mma16816(acc[mt][nt], al, bh[nt]);
                    mma16816(acc[mt][nt], ah, bl[nt]);
                }
            }
        }
        __syncthreads();
        if (s + 2 < nst) issue(s & 1, (s + 2) << 5);
    }

    // ---------------- epilogue ----------------
    #pragma unroll
    for (int mt = 0; mt < 4; mt++){
        #pragma unroll
        for (int nt = 0; nt < 4; nt++){
            int ca = n0 + (wn << 5) + (nt << 3) + tg * 2;
            #pragma unroll
            for (int half = 0; half < 2; half++){
                int row = m0 + (wm << 6) + (mt << 4) + g + (half << 3);
                float v0 = acc[mt][nt][half * 2];
                float v1 = acc[mt][nt][half * 2 + 1];
                if (EPI == 0){
                    float* Crow = C + (size_t)row * L_;
                    if (ca     < L_) Crow[ca]     = v0;
                    if (ca + 1 < L_) Crow[ca + 1] = v1;
                } else {
                    size_t o = (size_t)row * E_ + ca;
                    if (EPI == 1 || EPI == 3){ v0 += bias[ca]; v1 += bias[ca + 1]; }
                    if (EPI >= 2){
                        v0 += Xres[o];
                        v1 += Xres[o + 1];
                    }
                    if (EPI == 3){ v0 += tp[ca]; v1 += tp[ca + 1]; }
                    float2 f2; f2.x = v0; f2.y = v1;
                    *(float2*)(C + o) = f2;
                    if (EPI == 2){
                        bf16 h0 = __float2bfloat16(v0);
                        bf16 h1 = __float2bfloat16(v1);
                        bf16 l0 = __float2bfloat16(v0 - __bfloat162float(h0));
                        bf16 l1 = __float2bfloat16(v1 - __bfloat162float(h1));
                        __nv_bfloat162 hp; hp.x = h0; hp.y = h1;
                        __nv_bfloat162 lp; lp.x = l0; lp.y = l1;
                        *(__nv_bfloat162*)(Chi + o) = hp;
                        *(__nv_bfloat162*)(Clo + o) = lp;
                    }
                }
            }
        }
    }
}

// ---------------- prep kernels ----------------
__global__ __launch_bounds__(256)
void split_kernel(const float* __restrict__ x, bf16* __restrict__ hi,
                  bf16* __restrict__ lo, int n)
{
    int i = blockIdx.x * 256 + threadIdx.x;
    if (i >= n) return;
    float v = x[i];
    bf16 h = __float2bfloat16(v);
    hi[i] = h;
    lo[i] = __float2bfloat16(v - __bfloat162float(h));
}

__global__ __launch_bounds__(256)
void transW_kernel(const float* __restrict__ W, bf16* __restrict__ Thi,
                   bf16* __restrict__ Tlo)
{
    __shared__ float t[32][33];
    int k0 = blockIdx.x * 32, n0 = blockIdx.y * 32;
    int tx = threadIdx.x, ty = threadIdx.y;   // 32x8
    #pragma unroll
    for (int i = 0; i < 4; i++)
        t[ty + 8 * i][tx] = W[(size_t)(k0 + ty + 8 * i) * E_ + n0 + tx];
    __syncthreads();
    #pragma unroll
    for (int i = 0; i < 4; i++){
        float v = t[tx][ty + 8 * i];
        size_t o = (size_t)(n0 + ty + 8 * i) * E_ + k0 + tx;
        bf16 h = __float2bfloat16(v);
        Thi[o] = h;
        Tlo[o] = __float2bfloat16(v - __bfloat162float(h));
    }
}

__global__ __launch_bounds__(256)
void tePad_kernel(const float* __restrict__ TE, bf16* __restrict__ hi,
                  bf16* __restrict__ lo)
{
    int i = blockIdx.x * 256 + threadIdx.x;    // over 128*768
    if (i >= 128 * E_) return;
    int l = i / E_, e = i % E_;
    float v = (l < L_) ? TE[(size_t)l * E_ + e] : 0.f;
    bf16 h = __float2bfloat16(v);
    hi[i] = h;
    lo[i] = __float2bfloat16(v - __bfloat162float(h));
}

__global__ __launch_bounds__(256)
void teT_kernel(const float* __restrict__ TE, bf16* __restrict__ hi,
                bf16* __restrict__ lo)
{
    int i = blockIdx.x * 256 + threadIdx.x;    // over 768*128
    if (i >= E_ * 128) return;
    int e = i >> 7, l = i & 127;
    float v = (l < L_) ? TE[(size_t)l * E_ + e] : 0.f;
    bf16 h = __float2bfloat16(v);
    hi[i] = h;
    lo[i] = __float2bfloat16(v - __bfloat162float(h));
}

__global__ __launch_bounds__(256)
void biasq_kernel(const float* __restrict__ tp, const float* __restrict__ Wq,
                  const float* __restrict__ bq, float* __restrict__ out)
{
    int n = blockIdx.x * 256 + threadIdx.x;
    if (n >= E_) return;
    float acc = bq[n];
    for (int k2 = 0; k2 < E_; k2++) acc += tp[k2] * Wq[(size_t)k2 * E_ + n];
    out[n] = acc;
}

// ---------------- softmax over L=100, writes bf16 split padded to 128 ----------------
__global__ __launch_bounds__(256)
void softmax100_kernel(const float* __restrict__ scores,
                       bf16* __restrict__ atthi, bf16* __restrict__ attlo)
{
    int warp = (blockIdx.x * blockDim.x + threadIdx.x) >> 5;
    int lane = threadIdx.x & 31;
    if (warp >= MROWS) return;
    const float* s = scores + (size_t)warp * L_;
    float v[4];
    float mx = -INFINITY;
    #pragma unroll
    for (int i = 0; i < 4; i++){
        int l = lane + i * 32;
        v[i] = (l < L_) ? s[l] : -INFINITY;
        mx = fmaxf(mx, v[i]);
    }
    #pragma unroll
    for (int w = 16; w; w >>= 1) mx = fmaxf(mx, __shfl_xor_sync(0xffffffffu, mx, w));
    float sum = 0.f;
    #pragma unroll
    for (int i = 0; i < 4; i++){
        int l = lane + i * 32;
        v[i] = (l < L_) ? expf(v[i] - mx) : 0.f;
        sum += v[i];
    }
    #pragma unroll
    for (int w = 16; w; w >>= 1) sum += __shfl_xor_sync(0xffffffffu, sum, w);
    float inv = 1.f / sum;
    #pragma unroll
    for (int i = 0; i < 4; i++){
        int l = lane + i * 32;
        float p = (l < L_) ? v[i] * inv : 0.f;
        bf16 h = __float2bfloat16(p);
        atthi[(size_t)warp * 128 + l] = h;
        attlo[(size_t)warp * 128 + l] = __float2bfloat16(p - __bfloat162float(h));
    }
}

// ---------------- flash attention (SIMT fp32), ctx written as bf16 split ----------------
#define FSTR 65
extern __shared__ float fsm[];
__global__ __launch_bounds__(256)
void flash_kernel(const float* __restrict__ q, const float* __restrict__ k,
                  const float* __restrict__ v, const float* __restrict__ amask,
                  bf16* __restrict__ ctxhi, bf16* __restrict__ ctxlo)
{
    const int b = blockIdx.z, h = blockIdx.y, q0 = blockIdx.x * 64;
    const int tid = threadIdx.x;
    const int tx = tid & 15, ty = tid >> 4;
    float* Qs = fsm;
    float* Ks = Qs + 64 * FSTR;
    float* Vs = Ks + 64 * FSTR;
    float* Ps = Vs + 64 * FSTR;

    for (int idx = tid; idx < 64 * 64; idx += 256){
        int r = idx >> 6, d = idx & 63;
        Qs[r * FSTR + d] = q[(((size_t)b * T_ + q0 + r) * H_ + h) * D_ + d] * 0.125f;
    }

    float m_prev[4], l_prev[4], O[4][4] = {};
    #pragma unroll
    for (int i = 0; i < 4; i++){ m_prev[i] = -INFINITY; l_prev[i] = 0.f; }

    for (int kt = 0; kt < T_; kt += 64){
        for (int idx = tid; idx < 64 * 64; idx += 256){
            int r = idx >> 6, d = idx & 63;
            size_t base = (((size_t)b * T_ + kt + r) * H_ + h) * D_ + d;
            Ks[r * FSTR + d] = k[base];
            Vs[r * FSTR + d] = v[base];
        }
        __syncthreads();

        float s[4][4] = {};
        #pragma unroll 8
        for (int d = 0; d < 64; d++){
            float a[4], bb[4];
            #pragma unroll
            for (int i = 0; i < 4; i++) a[i] = Qs[(ty * 4 + i) * FSTR + d];
            #pragma unroll
            for (int j = 0; j < 4; j++) bb[j] = Ks[(tx * 4 + j) * FSTR + d];
            #pragma unroll
            for (int i = 0; i < 4; i++)
                #pragma unroll
                for (int j = 0; j < 4; j++)
                    s[i][j] += a[i] * bb[j];
        }

        #pragma unroll
        for (int j = 0; j < 4; j++){
            int kg = kt + tx * 4 + j;
            float mbias = (1.f - amask[(size_t)b * T_ + kg]) * NEGBIG;
            #pragma unroll
            for (int i = 0; i < 4; i++){
                int qg = q0 + ty * 4 + i;
                s[i][j] += mbias + ((qg == kg) ? NEGBIG : 0.f);
            }
        }

        #pragma unroll
        for (int i = 0; i < 4; i++){
            float rm = fmaxf(fmaxf(s[i][0], s[i][1]), fmaxf(s[i][2], s[i][3]));
            #pragma unroll
            for (int w = 8; w; w >>= 1) rm = fmaxf(rm, __shfl_xor_sync(0xffffffffu, rm, w));
            float mnew = fmaxf(m_prev[i], rm);
            float corr = __expf(m_prev[i] - mnew);
            float rs = 0.f;
            #pragma unroll
            for (int j = 0; j < 4; j++){
                float p = __expf(s[i][j] - mnew);
                s[i][j] = p;
                rs += p;
            }
            #pragma unroll
            for (int w = 8; w; w >>= 1) rs += __shfl_xor_sync(0xffffffffu, rs, w);
            l_prev[i] = l_prev[i] * corr + rs;
            m_prev[i] = mnew;
            #pragma unroll
            for (int j = 0; j < 4; j++) O[i][j] *= corr;
        }

        #pragma unroll
        for (int i = 0; i < 4; i++)
            #pragma unroll
            for (int j = 0; j < 4; j++)
                Ps[(ty * 4 + i) * FSTR + tx * 4 + j] = s[i][j];
        __syncthreads();

        #pragma unroll 8
        for (int kk = 0; kk < 64; kk++){
            float p[4], vv[4];
            #pragma unroll
            for (int i = 0; i < 4; i++) p[i] = Ps[(ty * 4 + i) * FSTR + kk];
            #pragma unroll
            for (int j = 0; j < 4; j++) vv[j] = Vs[kk * FSTR + tx * 4 + j];
            #pragma unroll
            for (int i = 0; i < 4; i++)
                #pragma unroll
                for (int j = 0; j < 4; j++)
                    O[i][j] += p[i] * vv[j];
        }
        __syncthreads();
    }

    #pragma unroll
    for (int i = 0; i < 4; i++){
        float inv = 1.f / l_prev[i];
        int qg = q0 + ty * 4 + i;
        #pragma unroll
        for (int j = 0; j < 4; j++){
            float val = O[i][j] * inv;
            size_t o = (((size_t)b * T_ + qg) * H_ + h) * D_ + tx * 4 + j;
            bf16 hh = __float2bfloat16(val);
            ctxhi[o] = hh;
            ctxlo[o] = __float2bfloat16(val - __bfloat162float(hh));
        }
    }
}

// ---------------- LayerNorm + final residual ----------------
__global__ __launch_bounds__(256)
void ln_kernel(const float* __restrict__ z, const float* __restrict__ g,
               const float* __restrict__ bb, const float* __restrict__ ht,
               float* __restrict__ out)
{
    const int m = blockIdx.x;
    const int t = threadIdx.x;
    __shared__ float buf[E_];
    __shared__ float red[8];
    const int lane = t & 31, wrp = t >> 5;

    float s = 0.f;
    for (int e = t; e < E_; e += 256){
        float x = z[(size_t)m * E_ + e];
        buf[e] = x;
        s += x;
    }
    #pragma unroll
    for (int w = 16; w; w >>= 1) s += __shfl_xor_sync(0xffffffffu, s, w);
    if (lane == 0) red[wrp] = s;
    __syncthreads();
    float mu = 0.f;
    #pragma unroll
    for (int i = 0; i < 8; i++) mu += red[i];
    mu *= (1.f / E_);
    __syncthreads();

    float vs = 0.f;
    for (int e = t; e < E_; e += 256){
        float d = buf[e] - mu;
        vs += d * d;
    }
    #pragma unroll
    for (int w = 16; w; w >>= 1) vs += __shfl_xor_sync(0xffffffffu, vs, w);
    if (lane == 0) red[wrp] = vs;
    __syncthreads();
    float var = 0.f;
    #pragma unroll
    for (int i = 0; i < 8; i++) var += red[i];
    var *= (1.f / E_);
    float rs = rsqrtf(var + 1e-12f);

    for (int e = t; e < E_; e += 256){
        out[(size_t)m * E_ + e] =
            (buf[e] - mu) * rs * g[e] + bb[e] + ht[(size_t)m * E_ + e];
    }
}

// ---------------- launch ----------------
extern "C" void kernel_launch(void* const* d_in, const int* in_sizes, int n_in,
                              void* d_out, int out_size)
{
    const float* X    = (const float*)d_in[0];
    const float* amsk = (const float*)d_in[1];
    const float* TE   = (const float*)d_in[2];
    const float* tp   = (const float*)d_in[3];
    const float* Wq   = (const float*)d_in[4];
    const float* bq   = (const float*)d_in[5];
    const float* Wk   = (const float*)d_in[6];
    const float* bk   = (const float*)d_in[7];
    const float* Wv   = (const float*)d_in[8];
    const float* bv   = (const float*)d_in[9];
    const float* Wo   = (const float*)d_in[10];
    const float* bo   = (const float*)d_in[11];
    const float* lng  = (const float*)d_in[12];
    const float* lnb  = (const float*)d_in[13];

    float* out    = (float*)d_out;
    float* scores = out + (size_t)MROWS * E_;

    bf16 *pXhi, *pXlo, *patthi, *pattlo, *phthi, *phtlo, *pctxhi, *pctxlo;
    bf16 *pWq1, *pWq2, *pWk1, *pWk2, *pWv1, *pWv2, *pWo1, *pWo2;
    bf16 *pTE1, *pTE2, *pTEt1, *pTEt2;
    float *pht, *pq, *pk, *pv, *pz, *pbq2;
    cudaGetSymbolAddress((void**)&pXhi,   g_Xhi);
    cudaGetSymbolAddress((void**)&pXlo,   g_Xlo);
    cudaGetSymbolAddress((void**)&patthi, g_atthi);
    cudaGetSymbolAddress((void**)&pattlo, g_attlo);
    cudaGetSymbolAddress((void**)&pht,    g_ht);
    cudaGetSymbolAddress((void**)&phthi,  g_hthi);
    cudaGetSymbolAddress((void**)&phtlo,  g_htlo);
    cudaGetSymbolAddress((void**)&pq,     g_q);
    cudaGetSymbolAddress((void**)&pk,     g_k);
    cudaGetSymbolAddress((void**)&pv,     g_v);
    cudaGetSymbolAddress((void**)&pctxhi, g_ctxhi);
    cudaGetSymbolAddress((void**)&pctxlo, g_ctxlo);
    cudaGetSymbolAddress((void**)&pz,     g_z);
    cudaGetSymbolAddress((void**)&pWq1,   g_Wqthi);
    cudaGetSymbolAddress((void**)&pWq2,   g_Wqtlo);
    cudaGetSymbolAddress((void**)&pWk1,   g_Wkthi);
    cudaGetSymbolAddress((void**)&pWk2,   g_Wktlo);
    cudaGetSymbolAddress((void**)&pWv1,   g_Wvthi);
    cudaGetSymbolAddress((void**)&pWv2,   g_Wvtlo);
    cudaGetSymbolAddress((void**)&pWo1,   g_Wothi);
    cudaGetSymbolAddress((void**)&pWo2,   g_Wotlo);
    cudaGetSymbolAddress((void**)&pTE1,   g_TEhi);
    cudaGetSymbolAddress((void**)&pTE2,   g_TElo);
    cudaGetSymbolAddress((void**)&pTEt1,  g_TEthi);
    cudaGetSymbolAddress((void**)&pTEt2,  g_TEtlo);
    cudaGetSymbolAddress((void**)&pbq2,   g_bq2);

    const int gsm = 2 * 4 * 128 * AST * (int)sizeof(bf16);   // 81920
    cudaFuncSetAttribute(mma_gemm<0>, cudaFuncAttributeMaxDynamicSharedMemorySize, gsm);
    cudaFuncSetAttribute(mma_gemm<1>, cudaFuncAttributeMaxDynamicSharedMemorySize, gsm);
    cudaFuncSetAttribute(mma_gemm<2>, cudaFuncAttributeMaxDynamicSharedMemorySize, gsm);
    cudaFuncSetAttribute(mma_gemm<3>, cudaFuncAttributeMaxDynamicSharedMemorySize, gsm);
    const int flash_smem = 4 * 64 * FSTR * sizeof(float);
    cudaFuncSetAttribute(flash_kernel, cudaFuncAttributeMaxDynamicSharedMemorySize,
                         flash_smem);

    dim3 blk(256);

    // ---- prep ----
    split_kernel<<<(MROWS * E_ + 255) / 256, blk>>>(X, pXhi, pXlo, MROWS * E_);
    {
        dim3 tg(24, 24), tb(32, 8);
        transW_kernel<<<tg, tb>>>(Wq, pWq1, pWq2);
        transW_kernel<<<tg, tb>>>(Wk, pWk1, pWk2);
        transW_kernel<<<tg, tb>>>(Wv, pWv1, pWv2);
        transW_kernel<<<tg, tb>>>(Wo, pWo1, pWo2);
    }
    tePad_kernel<<<(128 * E_ + 255) / 256, blk>>>(TE, pTE1, pTE2);
    teT_kernel<<<(E_ * 128 + 255) / 256, blk>>>(TE, pTEt1, pTEt2);
    biasq_kernel<<<3, blk>>>(tp, Wq, bq, pbq2);

    // ---- 1) scores = X @ TE^T ----
    mma_gemm<0><<<dim3(1, 64), blk, gsm>>>(pXhi, pXlo, E_, pTE1, pTE2, E_, E_,
                                           nullptr, nullptr, nullptr,
                                           scores, nullptr, nullptr);
    // ---- 2) att = softmax(scores), bf16 split padded ----
    softmax100_kernel<<<MROWS / 8, blk>>>(scores, patthi, pattlo);
    // ---- 3) h_truth = att @ TE + X (fp32 + bf16 split) ----
    mma_gemm<2><<<dim3(6, 64), blk, gsm>>>(patthi, pattlo, 128, pTEt1, pTEt2, 128, 128,
                                           nullptr, X, nullptr,
                                           pht, phthi, phtlo);
    // ---- 4) q = X @ Wq + (bq + tp@Wq) ----
    mma_gemm<1><<<dim3(6, 64), blk, gsm>>>(pXhi, pXlo, E_, pWq1, pWq2, E_, E_,
                                           pbq2, nullptr, nullptr,
                                           pq, nullptr, nullptr);
    // ---- 5) k,v = h_truth @ Wk/Wv + b ----
    mma_gemm<1><<<dim3(6, 64), blk, gsm>>>(phthi, phtlo, E_, pWk1, pWk2, E_, E_,
                                           bk, nullptr, nullptr,
                                           pk, nullptr, nullptr);
    mma_gemm<1><<<dim3(6, 64), blk, gsm>>>(phthi, phtlo, E_, pWv1, pWv2, E_, E_,
                                           bv, nullptr, nullptr,
                                           pv, nullptr, nullptr);
    // ---- 6) flash attention ----
    {
        dim3 grid(T_ / 64, H_, B_);
        flash_kernel<<<grid, blk, flash_smem>>>(pq, pk, pv, amsk, pctxhi, pctxlo);
    }
    // ---- 7) z = ctx @ Wo + bo + X + tp ----
    mma_gemm<3><<<dim3(6, 64), blk, gsm>>>(pctxhi, pctxlo, E_, pWo1, pWo2, E_, E_,
                                           bo, X, tp,
                                           pz, nullptr, nullptr);
    // ---- 8) out = LN(z) + h_truth ----
    ln_kernel<<<MROWS, blk>>>(pz, lng, lnb, pht, out);
}

// round 5
// speedup vs baseline: 2.5609x; 1.3265x over previous
#include <cuda_runtime.h>
#include <cuda_bf16.h>
#include <cstdint>
#include <cstddef>

#define B_ 16
#define T_ 512
#define E_ 768
#define H_ 12
#define D_ 64
#define L_ 100
#define MROWS (B_*T_)   // 8192
#define NEGBIG (-1e9f)
typedef __nv_bfloat16 bf16;

// ---------------- scratch (__device__ globals; alloc-free rule) ----------------
__device__ bf16 g_Xhi[MROWS*E_], g_Xlo[MROWS*E_];
__device__ bf16 g_atthi[MROWS*128], g_attlo[MROWS*128];
__device__ float g_ht[MROWS*E_];
__device__ bf16 g_hthi[MROWS*E_], g_htlo[MROWS*E_];
__device__ bf16 g_qhi[MROWS*E_], g_qlo[MROWS*E_];   // [b,h,t,d]
__device__ bf16 g_khi[MROWS*E_], g_klo[MROWS*E_];   // [b,h,t,d]
__device__ bf16 g_vhi[MROWS*E_], g_vlo[MROWS*E_];   // [b,h,d,t]
__device__ bf16 g_ctxhi[MROWS*E_], g_ctxlo[MROWS*E_];
__device__ float g_z[MROWS*E_];
__device__ bf16 g_Wqthi[E_*E_], g_Wqtlo[E_*E_];
__device__ bf16 g_Wkthi[E_*E_], g_Wktlo[E_*E_];
__device__ bf16 g_Wvthi[E_*E_], g_Wvtlo[E_*E_];
__device__ bf16 g_Wothi[E_*E_], g_Wotlo[E_*E_];
__device__ bf16 g_TEhi[128*E_], g_TElo[128*E_];
__device__ bf16 g_TEthi[E_*128], g_TEtlo[E_*128];
__device__ float g_bq2[E_];

// ---------------- helpers ----------------
__device__ __forceinline__ uint32_t smem_u32(const void* p){
    uint32_t a;
    asm("{ .reg .u64 t; cvta.to.shared.u64 t, %1; cvt.u32.u64 %0, t; }":"=r"(a):"l"(p));
    return a;
}
__device__ __forceinline__ void cp16(uint32_t dst, const void* src){
    asm volatile("cp.async.cg.shared.global [%0], [%1], 16;" :: "r"(dst), "l"(src));
}
#define CP_COMMIT() asm volatile("cp.async.commit_group;":::"memory")
#define CP_WAIT1()  asm volatile("cp.async.wait_group 1;":::"memory")
#define CP_WAIT0()  asm volatile("cp.async.wait_group 0;":::"memory")

__device__ __forceinline__ void mma16816(float* c, const uint32_t* a, const uint32_t* b){
    asm volatile(
        "mma.sync.aligned.m16n8k16.row.col.f32.bf16.bf16.f32 "
        "{%0,%1,%2,%3}, {%4,%5,%6,%7}, {%8,%9}, {%0,%1,%2,%3};"
        : "+f"(c[0]), "+f"(c[1]), "+f"(c[2]), "+f"(c[3])
        : "r"(a[0]), "r"(a[1]), "r"(a[2]), "r"(a[3]), "r"(b[0]), "r"(b[1]));
}

__device__ __forceinline__ void pack2(float a, float b, uint32_t& hi, uint32_t& lo){
    bf16 ha = __float2bfloat16(a), hb = __float2bfloat16(b);
    bf16 la = __float2bfloat16(a - __bfloat162float(ha));
    bf16 lb = __float2bfloat16(b - __bfloat162float(hb));
    __nv_bfloat162 hp; hp.x = ha; hp.y = hb;
    __nv_bfloat162 lp; lp.x = la; lp.y = lb;
    hi = *(uint32_t*)&hp;
    lo = *(uint32_t*)&lp;
}

#define AST 40   // GEMM smem row stride (bf16) for 32-wide k tiles

// ---------------- split-bf16 HMMA GEMM: C[M,N] = A @ B^T (+epilogue) ----------------
// EPI: 0 = scores (store [M,100], guard n<100)
//      1 = +bias, store fp32 [M,768]
//      2 = +Xres, store fp32 C and bf16 split Chi/Clo   (h_truth)
//      3 = +bias +Xres +tp, store fp32                  (z)
//      4 = +bias, *scale, store bf16 split in [b,h,t,d] (q, k)
//      5 = +bias, store bf16 split in [b,h,d,t]         (v)
template<int EPI>
__global__ __launch_bounds__(256)
void mma_gemm(const bf16* __restrict__ Ahi, const bf16* __restrict__ Alo, int lda,
              const bf16* __restrict__ Bhi, const bf16* __restrict__ Blo, int ldb,
              int K,
              const float* __restrict__ bias, const float* __restrict__ Xres,
              const float* __restrict__ tp, float scale,
              float* __restrict__ C,
              bf16* __restrict__ Chi, bf16* __restrict__ Clo)
{
    extern __shared__ bf16 smem[];   // [2 stages][4 mats][128*AST]
    const int tid = threadIdx.x;
    const int lane = tid & 31, wid = tid >> 5;
    const int m0 = blockIdx.y << 7, n0 = blockIdx.x << 7;
    const int wm = wid & 1, wn = wid >> 1;    // warp tile: 64x32
    const int g = lane >> 2, tg = lane & 3;

    float acc[4][4][4] = {};

    const bf16* srcs[4] = {Ahi, Alo, Bhi, Blo};
    const int   lds_[4] = {lda, lda, ldb, ldb};
    const int   r0s_[4] = {m0, m0, n0, n0};

    const int nst = K >> 5;

    auto issue = [&](int st, int k0){
        #pragma unroll
        for (int mat = 0; mat < 4; mat++){
            bf16* dstm = smem + ((st * 4 + mat) * 128 * AST);
            #pragma unroll
            for (int it = 0; it < 2; it++){
                int idx = tid + (it << 8);
                int r = idx >> 2, c = idx & 3;
                cp16(smem_u32(dstm + r * AST + c * 8),
                     srcs[mat] + (size_t)(r0s_[mat] + r) * lds_[mat] + k0 + c * 8);
            }
        }
        CP_COMMIT();
    };

    issue(0, 0);
    if (nst > 1) issue(1, 32);

    for (int s = 0; s < nst; s++){
        if (s + 1 < nst) CP_WAIT1(); else CP_WAIT0();
        __syncthreads();
        const bf16* As_hi = smem + (((s & 1) * 4 + 0) * 128 * AST);
        const bf16* As_lo = smem + (((s & 1) * 4 + 1) * 128 * AST);
        const bf16* Bs_hi = smem + (((s & 1) * 4 + 2) * 128 * AST);
        const bf16* Bs_lo = smem + (((s & 1) * 4 + 3) * 128 * AST);

        #pragma unroll
        for (int kh = 0; kh < 2; kh++){
            const int c0 = (kh << 4) + tg * 2;
            uint32_t bh[4][2], bl[4][2];
            #pragma unroll
            for (int nt = 0; nt < 4; nt++){
                int rn = (wn << 5) + (nt << 3) + g;
                bh[nt][0] = *(const uint32_t*)(Bs_hi + rn * AST + c0);
                bh[nt][1] = *(const uint32_t*)(Bs_hi + rn * AST + c0 + 8);
                bl[nt][0] = *(const uint32_t*)(Bs_lo + rn * AST + c0);
                bl[nt][1] = *(const uint32_t*)(Bs_lo + rn * AST + c0 + 8);
            }
            #pragma unroll
            for (int mt = 0; mt < 4; mt++){
                int ra = (wm << 6) + (mt << 4) + g;
                uint32_t ah[4], al[4];
                ah[0] = *(const uint32_t*)(As_hi + ra * AST + c0);
                ah[1] = *(const uint32_t*)(As_hi + (ra + 8) * AST + c0);
                ah[2] = *(const uint32_t*)(As_hi + ra * AST + c0 + 8);
                ah[3] = *(const uint32_t*)(As_hi + (ra + 8) * AST + c0 + 8);
                al[0] = *(const uint32_t*)(As_lo + ra * AST + c0);
                al[1] = *(const uint32_t*)(As_lo + (ra + 8) * AST + c0);
                al[2] = *(const uint32_t*)(As_lo + ra * AST + c0 + 8);
                al[3] = *(const uint32_t*)(As_lo + (ra + 8) * AST + c0 + 8);
                #pragma unroll
                for (int nt = 0; nt < 4; nt++){
                    mma16816(acc[mt][nt], ah, bh[nt]);
                    mma16816(acc[mt][nt], al, bh[nt]);
                    mma16816(acc[mt][nt], ah, bl[nt]);
                }
            }
        }
        __syncthreads();
        if (s + 2 < nst) issue(s & 1, (s + 2) << 5);
    }

    // ---------------- epilogue ----------------
    #pragma unroll
    for (int mt = 0; mt < 4; mt++){
        #pragma unroll
        for (int nt = 0; nt < 4; nt++){
            int ca = n0 + (wn << 5) + (nt << 3) + tg * 2;
            #pragma unroll
            for (int half = 0; half < 2; half++){
                int row = m0 + (wm << 6) + (mt << 4) + g + (half << 3);
                float v0 = acc[mt][nt][half * 2];
                float v1 = acc[mt][nt][half * 2 + 1];
                if (EPI == 0){
                    float* Crow = C + (size_t)row * L_;
                    if (ca     < L_) Crow[ca]     = v0;
                    if (ca + 1 < L_) Crow[ca + 1] = v1;
                } else if (EPI == 4 || EPI == 5){
                    v0 = (v0 + bias[ca]) * scale;
                    v1 = (v1 + bias[ca + 1]) * scale;
                    int bb = row >> 9, t = row & 511;
                    int hh = ca >> 6, d = ca & 63;
                    bf16 h0 = __float2bfloat16(v0);
                    bf16 h1 = __float2bfloat16(v1);
                    bf16 l0 = __float2bfloat16(v0 - __bfloat162float(h0));
                    bf16 l1 = __float2bfloat16(v1 - __bfloat162float(h1));
                    if (EPI == 4){
                        size_t dst = (((size_t)bb * H_ + hh) * T_ + t) * 64 + d;
                        __nv_bfloat162 hp; hp.x = h0; hp.y = h1;
                        __nv_bfloat162 lp; lp.x = l0; lp.y = l1;
                        *(__nv_bfloat162*)(Chi + dst) = hp;
                        *(__nv_bfloat162*)(Clo + dst) = lp;
                    } else {
                        size_t dst = (((size_t)bb * H_ + hh) * 64 + d) * T_ + t;
                        Chi[dst] = h0; Chi[dst + T_] = h1;
                        Clo[dst] = l0; Clo[dst + T_] = l1;
                    }
                } else {
                    size_t o = (size_t)row * E_ + ca;
                    if (EPI == 1 || EPI == 3){ v0 += bias[ca]; v1 += bias[ca + 1]; }
                    if (EPI >= 2){ v0 += Xres[o]; v1 += Xres[o + 1]; }
                    if (EPI == 3){ v0 += tp[ca]; v1 += tp[ca + 1]; }
                    float2 f2; f2.x = v0; f2.y = v1;
                    *(float2*)(C + o) = f2;
                    if (EPI == 2){
                        uint32_t hp, lp;
                        pack2(v0, v1, hp, lp);
                        *(uint32_t*)(Chi + o) = hp;
                        *(uint32_t*)(Clo + o) = lp;
                    }
                }
            }
        }
    }
}

// ---------------- prep kernels ----------------
__global__ __launch_bounds__(256)
void split_kernel(const float* __restrict__ x, bf16* __restrict__ hi,
                  bf16* __restrict__ lo, int n)
{
    int i = blockIdx.x * 256 + threadIdx.x;
    if (i >= n) return;
    float v = x[i];
    bf16 h = __float2bfloat16(v);
    hi[i] = h;
    lo[i] = __float2bfloat16(v - __bfloat162float(h));
}

__global__ __launch_bounds__(256)
void transW_kernel(const float* __restrict__ W, bf16* __restrict__ Thi,
                   bf16* __restrict__ Tlo)
{
    __shared__ float t[32][33];
    int k0 = blockIdx.x * 32, n0 = blockIdx.y * 32;
    int tx = threadIdx.x, ty = threadIdx.y;   // 32x8
    #pragma unroll
    for (int i = 0; i < 4; i++)
        t[ty + 8 * i][tx] = W[(size_t)(k0 + ty + 8 * i) * E_ + n0 + tx];
    __syncthreads();
    #pragma unroll
    for (int i = 0; i < 4; i++){
        float v = t[tx][ty + 8 * i];
        size_t o = (size_t)(n0 + ty + 8 * i) * E_ + k0 + tx;
        bf16 h = __float2bfloat16(v);
        Thi[o] = h;
        Tlo[o] = __float2bfloat16(v - __bfloat162float(h));
    }
}

__global__ __launch_bounds__(256)
void tePad_kernel(const float* __restrict__ TE, bf16* __restrict__ hi,
                  bf16* __restrict__ lo)
{
    int i = blockIdx.x * 256 + threadIdx.x;    // over 128*768
    if (i >= 128 * E_) return;
    int l = i / E_, e = i % E_;
    float v = (l < L_) ? TE[(size_t)l * E_ + e] : 0.f;
    bf16 h = __float2bfloat16(v);
    hi[i] = h;
    lo[i] = __float2bfloat16(v - __bfloat162float(h));
}

__global__ __launch_bounds__(256)
void teT_kernel(const float* __restrict__ TE, bf16* __restrict__ hi,
                bf16* __restrict__ lo)
{
    int i = blockIdx.x * 256 + threadIdx.x;    // over 768*128
    if (i >= E_ * 128) return;
    int e = i >> 7, l = i & 127;
    float v = (l < L_) ? TE[(size_t)l * E_ + e] : 0.f;
    bf16 h = __float2bfloat16(v);
    hi[i] = h;
    lo[i] = __float2bfloat16(v - __bfloat162float(h));
}

__global__ __launch_bounds__(256)
void biasq_kernel(const float* __restrict__ tp, const float* __restrict__ Wq,
                  const float* __restrict__ bq, float* __restrict__ out)
{
    int n = blockIdx.x * 256 + threadIdx.x;
    if (n >= E_) return;
    float acc = bq[n];
    for (int k2 = 0; k2 < E_; k2++) acc += tp[k2] * Wq[(size_t)k2 * E_ + n];
    out[n] = acc;
}

// ---------------- softmax over L=100, writes bf16 split padded to 128 ----------------
__global__ __launch_bounds__(256)
void softmax100_kernel(const float* __restrict__ scores,
                       bf16* __restrict__ atthi, bf16* __restrict__ attlo)
{
    int warp = (blockIdx.x * blockDim.x + threadIdx.x) >> 5;
    int lane = threadIdx.x & 31;
    if (warp >= MROWS) return;
    const float* s = scores + (size_t)warp * L_;
    float v[4];
    float mx = -INFINITY;
    #pragma unroll
    for (int i = 0; i < 4; i++){
        int l = lane + i * 32;
        v[i] = (l < L_) ? s[l] : -INFINITY;
        mx = fmaxf(mx, v[i]);
    }
    #pragma unroll
    for (int w = 16; w; w >>= 1) mx = fmaxf(mx, __shfl_xor_sync(0xffffffffu, mx, w));
    float sum = 0.f;
    #pragma unroll
    for (int i = 0; i < 4; i++){
        int l = lane + i * 32;
        v[i] = (l < L_) ? expf(v[i] - mx) : 0.f;
        sum += v[i];
    }
    #pragma unroll
    for (int w = 16; w; w >>= 1) sum += __shfl_xor_sync(0xffffffffu, sum, w);
    float inv = 1.f / sum;
    #pragma unroll
    for (int i = 0; i < 4; i++){
        int l = lane + i * 32;
        float p = (l < L_) ? v[i] * inv : 0.f;
        bf16 h = __float2bfloat16(p);
        atthi[(size_t)warp * 128 + l] = h;
        attlo[(size_t)warp * 128 + l] = __float2bfloat16(p - __bfloat162float(h));
    }
}

// ---------------- tensor-core flash attention (split-bf16, FA2 layout) ----------------
#define FST 72   // flash smem row stride (bf16)
__global__ __launch_bounds__(256)
void flash_mma(const bf16* __restrict__ qh_g, const bf16* __restrict__ ql_g,
               const bf16* __restrict__ kh_g, const bf16* __restrict__ kl_g,
               const bf16* __restrict__ vh_g, const bf16* __restrict__ vl_g,
               const float* __restrict__ amask,
               bf16* __restrict__ ctxhi, bf16* __restrict__ ctxlo)
{
    extern __shared__ bf16 fs[];
    const int b = blockIdx.z, h = blockIdx.y, q0 = blockIdx.x << 7;
    const int tid = threadIdx.x, lane = tid & 31, w = tid >> 5;
    const int g = lane >> 2, tg = lane & 3;
    const int bh = b * H_ + h;

    bf16* sQh = fs;
    bf16* sQl = fs + 9216;           // 128*72
    float* sM = (float*)(fs + 55296);

    // mask bias into smem
    sM[tid]       = (1.f - amask[(size_t)b * T_ + tid])       * NEGBIG;
    sM[tid + 256] = (1.f - amask[(size_t)b * T_ + tid + 256]) * NEGBIG;

    auto tilebase = [&](int buf, int mat){
        return fs + 18432 + buf * 18432 + mat * 4608;   // 64*72 per mat
    };

    // issue Q (hi+lo): 128 rows x 8 chunks x 2 mats
    #pragma unroll
    for (int it = 0; it < 8; it++){
        int mat = it >> 2;
        int idx = tid + ((it & 3) << 8);
        int r = idx >> 3, c = idx & 7;
        const bf16* src = (mat ? ql_g : qh_g) + ((size_t)bh * T_ + q0 + r) * 64 + c * 8;
        cp16(smem_u32((mat ? sQl : sQh) + r * FST + c * 8), src);
    }
    CP_COMMIT();

    auto issueT = [&](int buf, int kt){
        #pragma unroll
        for (int it = 0; it < 8; it++){
            int mat = it >> 1;
            int idx = tid + ((it & 1) << 8);
            int r = idx >> 3, c = idx & 7;
            const bf16* src;
            if (mat == 0)      src = kh_g + ((size_t)bh * T_ + kt * 64 + r) * 64 + c * 8;
            else if (mat == 1) src = kl_g + ((size_t)bh * T_ + kt * 64 + r) * 64 + c * 8;
            else if (mat == 2) src = vh_g + ((size_t)bh * 64 + r) * T_ + kt * 64 + c * 8;
            else               src = vl_g + ((size_t)bh * 64 + r) * T_ + kt * 64 + c * 8;
            cp16(smem_u32(tilebase(buf, mat) + r * FST + c * 8), src);
        }
        CP_COMMIT();
    };
    issueT(0, 0);
    issueT(1, 1);
    CP_WAIT1();            // Q + tile0 done
    __syncthreads();

    // Q frags (register-resident, reused over all k-tiles)
    uint32_t qh[4][4], ql[4][4];
    {
        int ra = (w << 4) + g;
        #pragma unroll
        for (int kb = 0; kb < 4; kb++){
            int c0 = (kb << 4) + (tg << 1);
            qh[kb][0] = *(const uint32_t*)(sQh + ra * FST + c0);
            qh[kb][1] = *(const uint32_t*)(sQh + (ra + 8) * FST + c0);
            qh[kb][2] = *(const uint32_t*)(sQh + ra * FST + c0 + 8);
            qh[kb][3] = *(const uint32_t*)(sQh + (ra + 8) * FST + c0 + 8);
            ql[kb][0] = *(const uint32_t*)(sQl + ra * FST + c0);
            ql[kb][1] = *(const uint32_t*)(sQl + (ra + 8) * FST + c0);
            ql[kb][2] = *(const uint32_t*)(sQl + ra * FST + c0 + 8);
            ql[kb][3] = *(const uint32_t*)(sQl + (ra + 8) * FST + c0 + 8);
        }
    }

    const int qg0 = q0 + (w << 4) + g, qg1 = qg0 + 8;
    float o[8][4] = {};
    float mp0 = -INFINITY, mp1 = -INFINITY, l0 = 0.f, l1 = 0.f;

    for (int kt = 0; kt < 8; kt++){
        if (kt){
            if (kt < 7) CP_WAIT1(); else CP_WAIT0();
            __syncthreads();
        }
        const bf16* Kh = tilebase(kt & 1, 0);
        const bf16* Kl = tilebase(kt & 1, 1);
        const bf16* Vh = tilebase(kt & 1, 2);
        const bf16* Vl = tilebase(kt & 1, 3);

        // S = Q @ K^T  (128x64 per CTA; 16x64 per warp)
        float s[8][4] = {};
        #pragma unroll
        for (int nf = 0; nf < 8; nf++){
            int kr = (nf << 3) + g;
            #pragma unroll
            for (int kb = 0; kb < 4; kb++){
                int c0 = (kb << 4) + (tg << 1);
                uint32_t bh2[2], bl2[2];
                bh2[0] = *(const uint32_t*)(Kh + kr * FST + c0);
                bh2[1] = *(const uint32_t*)(Kh + kr * FST + c0 + 8);
                bl2[0] = *(const uint32_t*)(Kl + kr * FST + c0);
                bl2[1] = *(const uint32_t*)(Kl + kr * FST + c0 + 8);
                mma16816(s[nf], qh[kb], bh2);
                mma16816(s[nf], ql[kb], bh2);
                mma16816(s[nf], qh[kb], bl2);
            }
        }

        // mask + online softmax
        float rm0 = -INFINITY, rm1 = -INFINITY;
        #pragma unroll
        for (int nf = 0; nf < 8; nf++){
            int cg = (kt << 6) + (nf << 3) + (tg << 1);
            float ma = sM[cg], mb = sM[cg + 1];
            s[nf][0] += ma + ((cg     == qg0) ? NEGBIG : 0.f);
            s[nf][1] += mb + ((cg + 1 == qg0) ? NEGBIG : 0.f);
            s[nf][2] += ma + ((cg     == qg1) ? NEGBIG : 0.f);
            s[nf][3] += mb + ((cg + 1 == qg1) ? NEGBIG : 0.f);
            rm0 = fmaxf(rm0, fmaxf(s[nf][0], s[nf][1]));
            rm1 = fmaxf(rm1, fmaxf(s[nf][2], s[nf][3]));
        }
        rm0 = fmaxf(rm0, __shfl_xor_sync(0xffffffffu, rm0, 1));
        rm0 = fmaxf(rm0, __shfl_xor_sync(0xffffffffu, rm0, 2));
        rm1 = fmaxf(rm1, __shfl_xor_sync(0xffffffffu, rm1, 1));
        rm1 = fmaxf(rm1, __shfl_xor_sync(0xffffffffu, rm1, 2));

        float mn0 = fmaxf(mp0, rm0), mn1 = fmaxf(mp1, rm1);
        float cf0 = __expf(mp0 - mn0), cf1 = __expf(mp1 - mn1);
        float rs0 = 0.f, rs1 = 0.f;
        #pragma unroll
        for (int nf = 0; nf < 8; nf++){
            s[nf][0] = __expf(s[nf][0] - mn0);
            s[nf][1] = __expf(s[nf][1] - mn0);
            s[nf][2] = __expf(s[nf][2] - mn1);
            s[nf][3] = __expf(s[nf][3] - mn1);
            rs0 += s[nf][0] + s[nf][1];
            rs1 += s[nf][2] + s[nf][3];
        }
        rs0 += __shfl_xor_sync(0xffffffffu, rs0, 1);
        rs0 += __shfl_xor_sync(0xffffffffu, rs0, 2);
        rs1 += __shfl_xor_sync(0xffffffffu, rs1, 1);
        rs1 += __shfl_xor_sync(0xffffffffu, rs1, 2);

        l0 = l0 * cf0 + rs0;
        l1 = l1 * cf1 + rs1;
        mp0 = mn0; mp1 = mn1;
        #pragma unroll
        for (int df = 0; df < 8; df++){
            o[df][0] *= cf0; o[df][1] *= cf0;
            o[df][2] *= cf1; o[df][3] *= cf1;
        }

        // pack P into A-frags (hi/lo)
        uint32_t ph[4][4], pl[4][4];
        #pragma unroll
        for (int kb = 0; kb < 4; kb++){
            pack2(s[2*kb][0],   s[2*kb][1],   ph[kb][0], pl[kb][0]);
            pack2(s[2*kb][2],   s[2*kb][3],   ph[kb][1], pl[kb][1]);
            pack2(s[2*kb+1][0], s[2*kb+1][1], ph[kb][2], pl[kb][2]);
            pack2(s[2*kb+1][2], s[2*kb+1][3], ph[kb][3], pl[kb][3]);
        }

        // O += P @ V   (V stored transposed [d][t])
        #pragma unroll
        for (int df = 0; df < 8; df++){
            int vr = (df << 3) + g;
            #pragma unroll
            for (int kb = 0; kb < 4; kb++){
                int c0 = (kb << 4) + (tg << 1);
                uint32_t vh2[2], vl2[2];
                vh2[0] = *(const uint32_t*)(Vh + vr * FST + c0);
                vh2[1] = *(const uint32_t*)(Vh + vr * FST + c0 + 8);
                vl2[0] = *(const uint32_t*)(Vl + vr * FST + c0);
                vl2[1] = *(const uint32_t*)(Vl + vr * FST + c0 + 8);
                mma16816(o[df], ph[kb], vh2);
                mma16816(o[df], pl[kb], vh2);
                mma16816(o[df], ph[kb], vl2);
            }
        }

        __syncthreads();
        if (kt + 2 < 8) issueT(kt & 1, kt + 2);
    }

    // write ctx (bf16 split) as [b*t, e] rows for the O-projection GEMM
    float i0 = 1.f / l0, i1 = 1.f / l1;
    size_t row0 = (size_t)b * T_ + qg0;
    size_t row1 = (size_t)b * T_ + qg1;
    #pragma unroll
    for (int df = 0; df < 8; df++){
        int d = h * 64 + (df << 3) + (tg << 1);
        uint32_t hp, lp;
        pack2(o[df][0] * i0, o[df][1] * i0, hp, lp);
        *(uint32_t*)(ctxhi + row0 * E_ + d) = hp;
        *(uint32_t*)(ctxlo + row0 * E_ + d) = lp;
        pack2(o[df][2] * i1, o[df][3] * i1, hp, lp);
        *(uint32_t*)(ctxhi + row1 * E_ + d) = hp;
        *(uint32_t*)(ctxlo + row1 * E_ + d) = lp;
    }
}

// ---------------- LayerNorm + final residual ----------------
__global__ __launch_bounds__(256)
void ln_kernel(const float* __restrict__ z, const float* __restrict__ g,
               const float* __restrict__ bb, const float* __restrict__ ht,
               float* __restrict__ out)
{
    const int m = blockIdx.x;
    const int t = threadIdx.x;
    __shared__ float buf[E_];
    __shared__ float red[8];
    const int lane = t & 31, wrp = t >> 5;

    float s = 0.f;
    for (int e = t; e < E_; e += 256){
        float x = z[(size_t)m * E_ + e];
        buf[e] = x;
        s += x;
    }
    #pragma unroll
    for (int w = 16; w; w >>= 1) s += __shfl_xor_sync(0xffffffffu, s, w);
    if (lane == 0) red[wrp] = s;
    __syncthreads();
    float mu = 0.f;
    #pragma unroll
    for (int i = 0; i < 8; i++) mu += red[i];
    mu *= (1.f / E_);
    __syncthreads();

    float vs = 0.f;
    for (int e = t; e < E_; e += 256){
        float d = buf[e] - mu;
        vs += d * d;
    }
    #pragma unroll
    for (int w = 16; w; w >>= 1) vs += __shfl_xor_sync(0xffffffffu, vs, w);
    if (lane == 0) red[wrp] = vs;
    __syncthreads();
    float var = 0.f;
    #pragma unroll
    for (int i = 0; i < 8; i++) var += red[i];
    var *= (1.f / E_);
    float rs = rsqrtf(var + 1e-12f);

    for (int e = t; e < E_; e += 256){
        out[(size_t)m * E_ + e] =
            (buf[e] - mu) * rs * g[e] + bb[e] + ht[(size_t)m * E_ + e];
    }
}

// ---------------- launch ----------------
extern "C" void kernel_launch(void* const* d_in, const int* in_sizes, int n_in,
                              void* d_out, int out_size)
{
    const float* X    = (const float*)d_in[0];
    const float* amsk = (const float*)d_in[1];
    const float* TE   = (const float*)d_in[2];
    const float* tp   = (const float*)d_in[3];
    const float* Wq   = (const float*)d_in[4];
    const float* bq   = (const float*)d_in[5];
    const float* Wk   = (const float*)d_in[6];
    const float* bk   = (const float*)d_in[7];
    const float* Wv   = (const float*)d_in[8];
    const float* bv   = (const float*)d_in[9];
    const float* Wo   = (const float*)d_in[10];
    const float* bo   = (const float*)d_in[11];
    const float* lng  = (const float*)d_in[12];
    const float* lnb  = (const float*)d_in[13];

    float* out    = (float*)d_out;
    float* scores = out + (size_t)MROWS * E_;

    bf16 *pXhi, *pXlo, *patthi, *pattlo, *phthi, *phtlo, *pctxhi, *pctxlo;
    bf16 *pqhi, *pqlo, *pkhi, *pklo, *pvhi, *pvlo;
    bf16 *pWq1, *pWq2, *pWk1, *pWk2, *pWv1, *pWv2, *pWo1, *pWo2;
    bf16 *pTE1, *pTE2, *pTEt1, *pTEt2;
    float *pht, *pz, *pbq2;
    cudaGetSymbolAddress((void**)&pXhi,   g_Xhi);
    cudaGetSymbolAddress((void**)&pXlo,   g_Xlo);
    cudaGetSymbolAddress((void**)&patthi, g_atthi);
    cudaGetSymbolAddress((void**)&pattlo, g_attlo);
    cudaGetSymbolAddress((void**)&pht,    g_ht);
    cudaGetSymbolAddress((void**)&phthi,  g_hthi);
    cudaGetSymbolAddress((void**)&phtlo,  g_htlo);
    cudaGetSymbolAddress((void**)&pqhi,   g_qhi);
    cudaGetSymbolAddress((void**)&pqlo,   g_qlo);
    cudaGetSymbolAddress((void**)&pkhi,   g_khi);
    cudaGetSymbolAddress((void**)&pklo,   g_klo);
    cudaGetSymbolAddress((void**)&pvhi,   g_vhi);
    cudaGetSymbolAddress((void**)&pvlo,   g_vlo);
    cudaGetSymbolAddress((void**)&pctxhi, g_ctxhi);
    cudaGetSymbolAddress((void**)&pctxlo, g_ctxlo);
    cudaGetSymbolAddress((void**)&pz,     g_z);
    cudaGetSymbolAddress((void**)&pWq1,   g_Wqthi);
    cudaGetSymbolAddress((void**)&pWq2,   g_Wqtlo);
    cudaGetSymbolAddress((void**)&pWk1,   g_Wkthi);
    cudaGetSymbolAddress((void**)&pWk2,   g_Wktlo);
    cudaGetSymbolAddress((void**)&pWv1,   g_Wvthi);
    cudaGetSymbolAddress((void**)&pWv2,   g_Wvtlo);
    cudaGetSymbolAddress((void**)&pWo1,   g_Wothi);
    cudaGetSymbolAddress((void**)&pWo2,   g_Wotlo);
    cudaGetSymbolAddress((void**)&pTE1,   g_TEhi);
    cudaGetSymbolAddress((void**)&pTE2,   g_TElo);
    cudaGetSymbolAddress((void**)&pTEt1,  g_TEthi);
    cudaGetSymbolAddress((void**)&pTEt2,  g_TEtlo);
    cudaGetSymbolAddress((void**)&pbq2,   g_bq2);

    const int gsm = 2 * 4 * 128 * AST * (int)sizeof(bf16);   // 81920
    cudaFuncSetAttribute(mma_gemm<0>, cudaFuncAttributeMaxDynamicSharedMemorySize, gsm);
    cudaFuncSetAttribute(mma_gemm<1>, cudaFuncAttributeMaxDynamicSharedMemorySize, gsm);
    cudaFuncSetAttribute(mma_gemm<2>, cudaFuncAttributeMaxDynamicSharedMemorySize, gsm);
    cudaFuncSetAttribute(mma_gemm<3>, cudaFuncAttributeMaxDynamicSharedMemorySize, gsm);
    cudaFuncSetAttribute(mma_gemm<4>, cudaFuncAttributeMaxDynamicSharedMemorySize, gsm);
    cudaFuncSetAttribute(mma_gemm<5>, cudaFuncAttributeMaxDynamicSharedMemorySize, gsm);
    const int fsm_bytes = 55296 * (int)sizeof(bf16) + 512 * (int)sizeof(float); // 112640
    cudaFuncSetAttribute(flash_mma, cudaFuncAttributeMaxDynamicSharedMemorySize,
                         fsm_bytes);

    dim3 blk(256);

    // ---- prep ----
    split_kernel<<<(MROWS * E_ + 255) / 256, blk>>>(X, pXhi, pXlo, MROWS * E_);
    {
        dim3 tg(24, 24), tb(32, 8);
        transW_kernel<<<tg, tb>>>(Wq, pWq1, pWq2);
        transW_kernel<<<tg, tb>>>(Wk, pWk1, pWk2);
        transW_kernel<<<tg, tb>>>(Wv, pWv1, pWv2);
        transW_kernel<<<tg, tb>>>(Wo, pWo1, pWo2);
    }
    tePad_kernel<<<(128 * E_ + 255) / 256, blk>>>(TE, pTE1, pTE2);
    teT_kernel<<<(E_ * 128 + 255) / 256, blk>>>(TE, pTEt1, pTEt2);
    biasq_kernel<<<3, blk>>>(tp, Wq, bq, pbq2);

    // ---- 1) scores = X @ TE^T ----
    mma_gemm<0><<<dim3(1, 64), blk, gsm>>>(pXhi, pXlo, E_, pTE1, pTE2, E_, E_,
                                           nullptr, nullptr, nullptr, 1.f,
                                           scores, nullptr, nullptr);
    // ---- 2) att = softmax(scores), bf16 split padded ----
    softmax100_kernel<<<MROWS / 8, blk>>>(scores, patthi, pattlo);
    // ---- 3) h_truth = att @ TE + X (fp32 + bf16 split) ----
    mma_gemm<2><<<dim3(6, 64), blk, gsm>>>(patthi, pattlo, 128, pTEt1, pTEt2, 128, 128,
                                           nullptr, X, nullptr, 1.f,
                                           pht, phthi, phtlo);
    // ---- 4) q = (X @ Wq + bq + tp@Wq) * 0.125, split [b,h,t,d] ----
    mma_gemm<4><<<dim3(6, 64), blk, gsm>>>(pXhi, pXlo, E_, pWq1, pWq2, E_, E_,
                                           pbq2, nullptr, nullptr, 0.125f,
                                           nullptr, pqhi, pqlo);
    // ---- 5) k, v ----
    mma_gemm<4><<<dim3(6, 64), blk, gsm>>>(phthi, phtlo, E_, pWk1, pWk2, E_, E_,
                                           bk, nullptr, nullptr, 1.f,
                                           nullptr, pkhi, pklo);
    mma_gemm<5><<<dim3(6, 64), blk, gsm>>>(phthi, phtlo, E_, pWv1, pWv2, E_, E_,
                                           bv, nullptr, nullptr, 1.f,
                                           nullptr, pvhi, pvlo);
    // ---- 6) flash attention (tensor cores) ----
    flash_mma<<<dim3(4, H_, B_), blk, fsm_bytes>>>(pqhi, pqlo, pkhi, pklo,
                                                   pvhi, pvlo, amsk,
                                                   pctxhi, pctxlo);
    // ---- 7) z = ctx @ Wo + bo + X + tp ----
    mma_gemm<3><<<dim3(6, 64), blk, gsm>>>(pctxhi, pctxlo, E_, pWo1, pWo2, E_, E_,
                                           bo, X, tp, 1.f,
                                           pz, nullptr, nullptr);
    // ---- 8) out = LN(z) + h_truth ----
    ln_kernel<<<MROWS, blk>>>(pz, lng, lnb, pht, out);
}

// round 6
// speedup vs baseline: 2.9335x; 1.1455x over previous
#include <cuda_runtime.h>
#include <cuda_bf16.h>
#include <cstdint>
#include <cstddef>

#define B_ 16
#define T_ 512
#define E_ 768
#define H_ 12
#define D_ 64
#define L_ 100
#define MROWS (B_*T_)   // 8192
#define NEGBIG (-1e9f)
typedef __nv_bfloat16 bf16;

// ---------------- scratch (__device__ globals; alloc-free rule) ----------------
__device__ bf16 g_Xhi[MROWS*E_], g_Xlo[MROWS*E_];
__device__ bf16 g_atthi[MROWS*128], g_attlo[MROWS*128];
__device__ float g_ht[MROWS*E_];
__device__ bf16 g_hthi[MROWS*E_], g_htlo[MROWS*E_];
__device__ bf16 g_qhi[MROWS*E_], g_qlo[MROWS*E_];   // [b,h,t,d]
__device__ bf16 g_khi[MROWS*E_], g_klo[MROWS*E_];   // [b,h,t,d]
__device__ bf16 g_vhi[MROWS*E_], g_vlo[MROWS*E_];   // [b,h,d,t]
__device__ bf16 g_ctxhi[MROWS*E_], g_ctxlo[MROWS*E_];
__device__ float g_z[MROWS*E_];
__device__ bf16 g_Wqthi[E_*E_], g_Wqtlo[E_*E_];
__device__ bf16 g_Wkthi[E_*E_], g_Wktlo[E_*E_];
__device__ bf16 g_Wvthi[E_*E_], g_Wvtlo[E_*E_];
__device__ bf16 g_Wothi[E_*E_], g_Wotlo[E_*E_];
__device__ bf16 g_TEhi[128*E_], g_TElo[128*E_];
__device__ bf16 g_TEthi[E_*128], g_TEtlo[E_*128];
__device__ float g_bq2[E_];

// ---------------- helpers ----------------
__device__ __forceinline__ uint32_t smem_u32(const void* p){
    uint32_t a;
    asm("{ .reg .u64 t; cvta.to.shared.u64 t, %1; cvt.u32.u64 %0, t; }":"=r"(a):"l"(p));
    return a;
}
__device__ __forceinline__ void cp16(uint32_t dst, const void* src){
    asm volatile("cp.async.cg.shared.global [%0], [%1], 16;" :: "r"(dst), "l"(src));
}
#define CP_COMMIT() asm volatile("cp.async.commit_group;":::"memory")
#define CP_WAIT1()  asm volatile("cp.async.wait_group 1;":::"memory")
#define CP_WAIT0()  asm volatile("cp.async.wait_group 0;":::"memory")

__device__ __forceinline__ void mma16816(float* c, const uint32_t* a, const uint32_t* b){
    asm volatile(
        "mma.sync.aligned.m16n8k16.row.col.f32.bf16.bf16.f32 "
        "{%0,%1,%2,%3}, {%4,%5,%6,%7}, {%8,%9}, {%0,%1,%2,%3};"
        : "+f"(c[0]), "+f"(c[1]), "+f"(c[2]), "+f"(c[3])
        : "r"(a[0]), "r"(a[1]), "r"(a[2]), "r"(a[3]), "r"(b[0]), "r"(b[1]));
}
__device__ __forceinline__ void ldsm4(uint32_t* r, uint32_t addr){
    asm volatile("ldmatrix.sync.aligned.m8n8.x4.shared.b16 {%0,%1,%2,%3}, [%4];"
        : "=r"(r[0]), "=r"(r[1]), "=r"(r[2]), "=r"(r[3]) : "r"(addr));
}

__device__ __forceinline__ void pack2(float a, float b, uint32_t& hi, uint32_t& lo){
    bf16 ha = __float2bfloat16(a), hb = __float2bfloat16(b);
    bf16 la = __float2bfloat16(a - __bfloat162float(ha));
    bf16 lb = __float2bfloat16(b - __bfloat162float(hb));
    __nv_bfloat162 hp; hp.x = ha; hp.y = hb;
    __nv_bfloat162 lp; lp.x = la; lp.y = lb;
    hi = *(uint32_t*)&hp;
    lo = *(uint32_t*)&lp;
}

#define AST 40   // GEMM smem row stride (bf16); 80B rows, LDSM conflict-free

// ---------------- split-bf16 HMMA GEMM: C[M,N] = A @ B^T (+epilogue) ----------------
// EPI: 0 = scores (store [M,100], guard n<100)
//      1 = +bias, store fp32 [M,768]
//      2 = +Xres, store fp32 C and bf16 split Chi/Clo   (h_truth)
//      3 = +bias +Xres +tp, store fp32                  (z)
//      4 = +bias, *scale, store bf16 split in [b,h,t,d] (q, k)
//      5 = +bias, store bf16 split in [b,h,d,t]         (v)
template<int EPI>
__global__ __launch_bounds__(256, 2)
void mma_gemm(const bf16* __restrict__ Ahi, const bf16* __restrict__ Alo, int lda,
              const bf16* __restrict__ Bhi, const bf16* __restrict__ Blo, int ldb,
              int K,
              const float* __restrict__ bias, const float* __restrict__ Xres,
              const float* __restrict__ tp, float scale,
              float* __restrict__ C,
              bf16* __restrict__ Chi, bf16* __restrict__ Clo)
{
    extern __shared__ bf16 smem[];   // [2 stages][4 mats][128*AST]
    const int tid = threadIdx.x;
    const int lane = tid & 31, wid = tid >> 5;
    const int m0 = blockIdx.y << 7, n0 = blockIdx.x << 7;
    const int wm = wid & 1, wn = wid >> 1;    // warp tile: 64x32
    const int g = lane >> 2, tg = lane & 3;

    float acc[4][4][4] = {};

    const bf16* srcs[4] = {Ahi, Alo, Bhi, Blo};
    const int   lds_[4] = {lda, lda, ldb, ldb};
    const int   r0s_[4] = {m0, m0, n0, n0};

    const int nst = K >> 5;
    const uint32_t fs_u = smem_u32(smem);
    // LDSM per-lane offsets (bytes): A x4 covers 16 rows x 16 cols
    const uint32_t aoff = (uint32_t)(((wm << 6) + (lane & 15)) * 80 + ((lane >> 4) << 4));
    // B x4 covers 16 n-rows (2 frag-pairs) x 16 cols
    const uint32_t boff = (uint32_t)(((wn << 5) + ((lane >> 4) << 3) + (lane & 7)) * 80
                                     + (((lane >> 3) & 1) << 4));

    auto issue = [&](int st, int k0){
        #pragma unroll
        for (int mat = 0; mat < 4; mat++){
            bf16* dstm = smem + ((st * 4 + mat) * 128 * AST);
            #pragma unroll
            for (int it = 0; it < 2; it++){
                int idx = tid + (it << 8);
                int r = idx >> 2, c = idx & 3;
                cp16(smem_u32(dstm + r * AST + c * 8),
                     srcs[mat] + (size_t)(r0s_[mat] + r) * lds_[mat] + k0 + c * 8);
            }
        }
        CP_COMMIT();
    };

    issue(0, 0);
    if (nst > 1) issue(1, 32);

    for (int s = 0; s < nst; s++){
        if (s + 1 < nst) CP_WAIT1(); else CP_WAIT0();
        __syncthreads();
        const uint32_t stg = fs_u + (uint32_t)((s & 1) * 40960);

        #pragma unroll
        for (int kh = 0; kh < 2; kh++){
            const uint32_t kb32 = (uint32_t)(kh << 5);
            uint32_t bfh[8], bfl[8];
            ldsm4(bfh,     stg + 20480u + boff + kb32);
            ldsm4(bfh + 4, stg + 20480u + boff + 1280u + kb32);
            ldsm4(bfl,     stg + 30720u + boff + kb32);
            ldsm4(bfl + 4, stg + 30720u + boff + 1280u + kb32);
            #pragma unroll
            for (int mt = 0; mt < 4; mt++){
                uint32_t ah[4], al[4];
                ldsm4(ah, stg + aoff + (uint32_t)(mt * 1280) + kb32);
                ldsm4(al, stg + 10240u + aoff + (uint32_t)(mt * 1280) + kb32);
                #pragma unroll
                for (int nt = 0; nt < 4; nt++){
                    mma16816(acc[mt][nt], ah, bfh + nt * 2);
                    mma16816(acc[mt][nt], al, bfh + nt * 2);
                    mma16816(acc[mt][nt], ah, bfl + nt * 2);
                }
            }
        }
        __syncthreads();
        if (s + 2 < nst) issue(s & 1, (s + 2) << 5);
    }

    // ---------------- epilogue ----------------
    #pragma unroll
    for (int mt = 0; mt < 4; mt++){
        #pragma unroll
        for (int nt = 0; nt < 4; nt++){
            int ca = n0 + (wn << 5) + (nt << 3) + tg * 2;
            #pragma unroll
            for (int half = 0; half < 2; half++){
                int row = m0 + (wm << 6) + (mt << 4) + g + (half << 3);
                float v0 = acc[mt][nt][half * 2];
                float v1 = acc[mt][nt][half * 2 + 1];
                if (EPI == 0){
                    float* Crow = C + (size_t)row * L_;
                    if (ca     < L_) Crow[ca]     = v0;
                    if (ca + 1 < L_) Crow[ca + 1] = v1;
                } else if (EPI == 4 || EPI == 5){
                    v0 = (v0 + bias[ca]) * scale;
                    v1 = (v1 + bias[ca + 1]) * scale;
                    int bb = row >> 9, t = row & 511;
                    int hh = ca >> 6, d = ca & 63;
                    bf16 h0 = __float2bfloat16(v0);
                    bf16 h1 = __float2bfloat16(v1);
                    bf16 l0 = __float2bfloat16(v0 - __bfloat162float(h0));
                    bf16 l1 = __float2bfloat16(v1 - __bfloat162float(h1));
                    if (EPI == 4){
                        size_t dst = (((size_t)bb * H_ + hh) * T_ + t) * 64 + d;
                        __nv_bfloat162 hp; hp.x = h0; hp.y = h1;
                        __nv_bfloat162 lp; lp.x = l0; lp.y = l1;
                        *(__nv_bfloat162*)(Chi + dst) = hp;
                        *(__nv_bfloat162*)(Clo + dst) = lp;
                    } else {
                        size_t dst = (((size_t)bb * H_ + hh) * 64 + d) * T_ + t;
                        Chi[dst] = h0; Chi[dst + T_] = h1;
                        Clo[dst] = l0; Clo[dst + T_] = l1;
                    }
                } else {
                    size_t o = (size_t)row * E_ + ca;
                    if (EPI == 1 || EPI == 3){ v0 += bias[ca]; v1 += bias[ca + 1]; }
                    if (EPI >= 2){ v0 += Xres[o]; v1 += Xres[o + 1]; }
                    if (EPI == 3){ v0 += tp[ca]; v1 += tp[ca + 1]; }
                    float2 f2; f2.x = v0; f2.y = v1;
                    *(float2*)(C + o) = f2;
                    if (EPI == 2){
                        uint32_t hp, lp;
                        pack2(v0, v1, hp, lp);
                        *(uint32_t*)(Chi + o) = hp;
                        *(uint32_t*)(Clo + o) = lp;
                    }
                }
            }
        }
    }
}

// ---------------- prep kernels ----------------
__global__ __launch_bounds__(256)
void split_kernel(const float* __restrict__ x, bf16* __restrict__ hi,
                  bf16* __restrict__ lo, int n)
{
    int i = blockIdx.x * 256 + threadIdx.x;
    if (i >= n) return;
    float v = x[i];
    bf16 h = __float2bfloat16(v);
    hi[i] = h;
    lo[i] = __float2bfloat16(v - __bfloat162float(h));
}

__global__ __launch_bounds__(256)
void transW_kernel(const float* __restrict__ W, bf16* __restrict__ Thi,
                   bf16* __restrict__ Tlo)
{
    __shared__ float t[32][33];
    int k0 = blockIdx.x * 32, n0 = blockIdx.y * 32;
    int tx = threadIdx.x, ty = threadIdx.y;   // 32x8
    #pragma unroll
    for (int i = 0; i < 4; i++)
        t[ty + 8 * i][tx] = W[(size_t)(k0 + ty + 8 * i) * E_ + n0 + tx];
    __syncthreads();
    #pragma unroll
    for (int i = 0; i < 4; i++){
        float v = t[tx][ty + 8 * i];
        size_t o = (size_t)(n0 + ty + 8 * i) * E_ + k0 + tx;
        bf16 h = __float2bfloat16(v);
        Thi[o] = h;
        Tlo[o] = __float2bfloat16(v - __bfloat162float(h));
    }
}

__global__ __launch_bounds__(256)
void tePad_kernel(const float* __restrict__ TE, bf16* __restrict__ hi,
                  bf16* __restrict__ lo)
{
    int i = blockIdx.x * 256 + threadIdx.x;    // over 128*768
    if (i >= 128 * E_) return;
    int l = i / E_, e = i % E_;
    float v = (l < L_) ? TE[(size_t)l * E_ + e] : 0.f;
    bf16 h = __float2bfloat16(v);
    hi[i] = h;
    lo[i] = __float2bfloat16(v - __bfloat162float(h));
}

__global__ __launch_bounds__(256)
void teT_kernel(const float* __restrict__ TE, bf16* __restrict__ hi,
                bf16* __restrict__ lo)
{
    int i = blockIdx.x * 256 + threadIdx.x;    // over 768*128
    if (i >= E_ * 128) return;
    int e = i >> 7, l = i & 127;
    float v = (l < L_) ? TE[(size_t)l * E_ + e] : 0.f;
    bf16 h = __float2bfloat16(v);
    hi[i] = h;
    lo[i] = __float2bfloat16(v - __bfloat162float(h));
}

__global__ __launch_bounds__(256)
void biasq_kernel(const float* __restrict__ tp, const float* __restrict__ Wq,
                  const float* __restrict__ bq, float* __restrict__ out)
{
    int n = blockIdx.x * 256 + threadIdx.x;
    if (n >= E_) return;
    float acc = bq[n];
    for (int k2 = 0; k2 < E_; k2++) acc += tp[k2] * Wq[(size_t)k2 * E_ + n];
    out[n] = acc;
}

// ---------------- softmax over L=100, writes bf16 split padded to 128 ----------------
__global__ __launch_bounds__(256)
void softmax100_kernel(const float* __restrict__ scores,
                       bf16* __restrict__ atthi, bf16* __restrict__ attlo)
{
    int warp = (blockIdx.x * blockDim.x + threadIdx.x) >> 5;
    int lane = threadIdx.x & 31;
    if (warp >= MROWS) return;
    const float* s = scores + (size_t)warp * L_;
    float v[4];
    float mx = -INFINITY;
    #pragma unroll
    for (int i = 0; i < 4; i++){
        int l = lane + i * 32;
        v[i] = (l < L_) ? s[l] : -INFINITY;
        mx = fmaxf(mx, v[i]);
    }
    #pragma unroll
    for (int w = 16; w; w >>= 1) mx = fmaxf(mx, __shfl_xor_sync(0xffffffffu, mx, w));
    float sum = 0.f;
    #pragma unroll
    for (int i = 0; i < 4; i++){
        int l = lane + i * 32;
        v[i] = (l < L_) ? expf(v[i] - mx) : 0.f;
        sum += v[i];
    }
    #pragma unroll
    for (int w = 16; w; w >>= 1) sum += __shfl_xor_sync(0xffffffffu, sum, w);
    float inv = 1.f / sum;
    #pragma unroll
    for (int i = 0; i < 4; i++){
        int l = lane + i * 32;
        float p = (l < L_) ? v[i] * inv : 0.f;
        bf16 h = __float2bfloat16(p);
        atthi[(size_t)warp * 128 + l] = h;
        attlo[(size_t)warp * 128 + l] = __float2bfloat16(p - __bfloat162float(h));
    }
}

// ---------------- tensor-core flash attention (split-bf16, LDSM) ----------------
#define FST 72   // flash smem row stride (bf16); 144B rows, LDSM conflict-free
__global__ __launch_bounds__(256, 2)
void flash_mma(const bf16* __restrict__ qh_g, const bf16* __restrict__ ql_g,
               const bf16* __restrict__ kh_g, const bf16* __restrict__ kl_g,
               const bf16* __restrict__ vh_g, const bf16* __restrict__ vl_g,
               const float* __restrict__ amask,
               bf16* __restrict__ ctxhi, bf16* __restrict__ ctxlo)
{
    extern __shared__ bf16 fs[];
    const int b = blockIdx.z, h = blockIdx.y, q0 = blockIdx.x << 7;
    const int tid = threadIdx.x, lane = tid & 31, w = tid >> 5;
    const int g = lane >> 2, tg = lane & 3;
    const int bh = b * H_ + h;

    bf16* sQh = fs;
    bf16* sQl = fs + 9216;           // 128*72
    float* sM = (float*)(fs + 55296);
    const uint32_t fs_u = smem_u32(fs);

    // mask bias into smem
    sM[tid]       = (1.f - amask[(size_t)b * T_ + tid])       * NEGBIG;
    sM[tid + 256] = (1.f - amask[(size_t)b * T_ + tid + 256]) * NEGBIG;

    // LDSM per-lane offsets (bytes)
    const uint32_t qoff = (uint32_t)(((w << 4) + (lane & 15)) * 144 + ((lane >> 4) << 4));
    const uint32_t koff = (uint32_t)((((lane >> 4) << 3) + (lane & 7)) * 144
                                     + (((lane >> 3) & 1) << 4));

    // issue Q (hi+lo): 128 rows x 8 chunks x 2 mats
    #pragma unroll
    for (int it = 0; it < 8; it++){
        int mat = it >> 2;
        int idx = tid + ((it & 3) << 8);
        int r = idx >> 3, c = idx & 7;
        const bf16* src = (mat ? ql_g : qh_g) + ((size_t)bh * T_ + q0 + r) * 64 + c * 8;
        cp16(smem_u32((mat ? sQl : sQh) + r * FST + c * 8), src);
    }
    CP_COMMIT();

    auto issueT = [&](int buf, int kt){
        #pragma unroll
        for (int it = 0; it < 8; it++){
            int mat = it >> 1;
            int idx = tid + ((it & 1) << 8);
            int r = idx >> 3, c = idx & 7;
            const bf16* src;
            if (mat == 0)      src = kh_g + ((size_t)bh * T_ + kt * 64 + r) * 64 + c * 8;
            else if (mat == 1) src = kl_g + ((size_t)bh * T_ + kt * 64 + r) * 64 + c * 8;
            else if (mat == 2) src = vh_g + ((size_t)bh * 64 + r) * T_ + kt * 64 + c * 8;
            else               src = vl_g + ((size_t)bh * 64 + r) * T_ + kt * 64 + c * 8;
            cp16(smem_u32(fs + 18432 + buf * 18432 + mat * 4608 + r * FST + c * 8), src);
        }
        CP_COMMIT();
    };
    issueT(0, 0);
    issueT(1, 1);
    CP_WAIT1();            // Q + tile0 done
    __syncthreads();

    // Q frags (register-resident, reused over all k-tiles)
    uint32_t qh[4][4], ql[4][4];
    #pragma unroll
    for (int kb = 0; kb < 4; kb++){
        ldsm4(qh[kb], fs_u + qoff + (uint32_t)(kb << 5));
        ldsm4(ql[kb], fs_u + 18432u + qoff + (uint32_t)(kb << 5));
    }

    const int qg0 = q0 + (w << 4) + g, qg1 = qg0 + 8;
    float o[8][4] = {};
    float mp0 = -INFINITY, mp1 = -INFINITY, l0 = 0.f, l1 = 0.f;

    for (int kt = 0; kt < 8; kt++){
        if (kt){
            if (kt < 7) CP_WAIT1(); else CP_WAIT0();
            __syncthreads();
        }
        const uint32_t Kh_u = fs_u + 36864u + (uint32_t)((kt & 1) * 36864);
        const uint32_t Kl_u = Kh_u + 9216u;
        const uint32_t Vh_u = Kh_u + 18432u;
        const uint32_t Vl_u = Kh_u + 27648u;

        // S = Q @ K^T  (128x64 per CTA; 16x64 per warp)
        float s[8][4] = {};
        #pragma unroll
        for (int np = 0; np < 4; np++){
            #pragma unroll
            for (int kb = 0; kb < 4; kb++){
                uint32_t k4h[4], k4l[4];
                uint32_t off = koff + (uint32_t)(np * 2304) + (uint32_t)(kb << 5);
                ldsm4(k4h, Kh_u + off);
                ldsm4(k4l, Kl_u + off);
                mma16816(s[2*np],     qh[kb], k4h);
                mma16816(s[2*np],     ql[kb], k4h);
                mma16816(s[2*np],     qh[kb], k4l);
                mma16816(s[2*np+1],   qh[kb], k4h + 2);
                mma16816(s[2*np+1],   ql[kb], k4h + 2);
                mma16816(s[2*np+1],   qh[kb], k4l + 2);
            }
        }

        // mask + online softmax
        float rm0 = -INFINITY, rm1 = -INFINITY;
        #pragma unroll
        for (int nf = 0; nf < 8; nf++){
            int cg = (kt << 6) + (nf << 3) + (tg << 1);
            float ma = sM[cg], mb = sM[cg + 1];
            s[nf][0] += ma + ((cg     == qg0) ? NEGBIG : 0.f);
            s[nf][1] += mb + ((cg + 1 == qg0) ? NEGBIG : 0.f);
            s[nf][2] += ma + ((cg     == qg1) ? NEGBIG : 0.f);
            s[nf][3] += mb + ((cg + 1 == qg1) ? NEGBIG : 0.f);
            rm0 = fmaxf(rm0, fmaxf(s[nf][0], s[nf][1]));
            rm1 = fmaxf(rm1, fmaxf(s[nf][2], s[nf][3]));
        }
        rm0 = fmaxf(rm0, __shfl_xor_sync(0xffffffffu, rm0, 1));
        rm0 = fmaxf(rm0, __shfl_xor_sync(0xffffffffu, rm0, 2));
        rm1 = fmaxf(rm1, __shfl_xor_sync(0xffffffffu, rm1, 1));
        rm1 = fmaxf(rm1, __shfl_xor_sync(0xffffffffu, rm1, 2));

        float mn0 = fmaxf(mp0, rm0), mn1 = fmaxf(mp1, rm1);
        float cf0 = __expf(mp0 - mn0), cf1 = __expf(mp1 - mn1);
        float rs0 = 0.f, rs1 = 0.f;
        #pragma unroll
        for (int nf = 0; nf < 8; nf++){
            s[nf][0] = __expf(s[nf][0] - mn0);
            s[nf][1] = __expf(s[nf][1] - mn0);
            s[nf][2] = __expf(s[nf][2] - mn1);
            s[nf][3] = __expf(s[nf][3] - mn1);
            rs0 += s[nf][0] + s[nf][1];
            rs1 += s[nf][2] + s[nf][3];
        }
        rs0 += __shfl_xor_sync(0xffffffffu, rs0, 1);
        rs0 += __shfl_xor_sync(0xffffffffu, rs0, 2);
        rs1 += __shfl_xor_sync(0xffffffffu, rs1, 1);
        rs1 += __shfl_xor_sync(0xffffffffu, rs1, 2);

        l0 = l0 * cf0 + rs0;
        l1 = l1 * cf1 + rs1;
        mp0 = mn0; mp1 = mn1;
        #pragma unroll
        for (int df = 0; df < 8; df++){
            o[df][0] *= cf0; o[df][1] *= cf0;
            o[df][2] *= cf1; o[df][3] *= cf1;
        }

        // O += P @ V   (kb-outer: P frags live only 8 regs)
        #pragma unroll
        for (int kb = 0; kb < 4; kb++){
            uint32_t ph[4], pl[4];
            pack2(s[2*kb][0],   s[2*kb][1],   ph[0], pl[0]);
            pack2(s[2*kb][2],   s[2*kb][3],   ph[1], pl[1]);
            pack2(s[2*kb+1][0], s[2*kb+1][1], ph[2], pl[2]);
            pack2(s[2*kb+1][2], s[2*kb+1][3], ph[3], pl[3]);
            #pragma unroll
            for (int dp = 0; dp < 4; dp++){
                uint32_t v4h[4], v4l[4];
                uint32_t off = koff + (uint32_t)(dp * 2304) + (uint32_t)(kb << 5);
                ldsm4(v4h, Vh_u + off);
                ldsm4(v4l, Vl_u + off);
                mma16816(o[2*dp],   ph, v4h);
                mma16816(o[2*dp],   pl, v4h);
                mma16816(o[2*dp],   ph, v4l);
                mma16816(o[2*dp+1], ph, v4h + 2);
                mma16816(o[2*dp+1], pl, v4h + 2);
                mma16816(o[2*dp+1], ph, v4l + 2);
            }
        }

        __syncthreads();
        if (kt + 2 < 8) issueT(kt & 1, kt + 2);
    }

    // write ctx (bf16 split) as [b*t, e] rows for the O-projection GEMM
    float i0 = 1.f / l0, i1 = 1.f / l1;
    size_t row0 = (size_t)b * T_ + qg0;
    size_t row1 = (size_t)b * T_ + qg1;
    #pragma unroll
    for (int df = 0; df < 8; df++){
        int d = h * 64 + (df << 3) + (tg << 1);
        uint32_t hp, lp;
        pack2(o[df][0] * i0, o[df][1] * i0, hp, lp);
        *(uint32_t*)(ctxhi + row0 * E_ + d) = hp;
        *(uint32_t*)(ctxlo + row0 * E_ + d) = lp;
        pack2(o[df][2] * i1, o[df][3] * i1, hp, lp);
        *(uint32_t*)(ctxhi + row1 * E_ + d) = hp;
        *(uint32_t*)(ctxlo + row1 * E_ + d) = lp;
    }
}

// ---------------- LayerNorm + final residual ----------------
__global__ __launch_bounds__(256)
void ln_kernel(const float* __restrict__ z, const float* __restrict__ g,
               const float* __restrict__ bb, const float* __restrict__ ht,
               float* __restrict__ out)
{
    const int m = blockIdx.x;
    const int t = threadIdx.x;
    __shared__ float buf[E_];
    __shared__ float red[8];
    const int lane = t & 31, wrp = t >> 5;

    float s = 0.f;
    for (int e = t; e < E_; e += 256){
        float x = z[(size_t)m * E_ + e];
        buf[e] = x;
        s += x;
    }
    #pragma unroll
    for (int w = 16; w; w >>= 1) s += __shfl_xor_sync(0xffffffffu, s, w);
    if (lane == 0) red[wrp] = s;
    __syncthreads();
    float mu = 0.f;
    #pragma unroll
    for (int i = 0; i < 8; i++) mu += red[i];
    mu *= (1.f / E_);
    __syncthreads();

    float vs = 0.f;
    for (int e = t; e < E_; e += 256){
        float d = buf[e] - mu;
        vs += d * d;
    }
    #pragma unroll
    for (int w = 16; w; w >>= 1) vs += __shfl_xor_sync(0xffffffffu, vs, w);
    if (lane == 0) red[wrp] = vs;
    __syncthreads();
    float var = 0.f;
    #pragma unroll
    for (int i = 0; i < 8; i++) var += red[i];
    var *= (1.f / E_);
    float rs = rsqrtf(var + 1e-12f);

    for (int e = t; e < E_; e += 256){
        out[(size_t)m * E_ + e] =
            (buf[e] - mu) * rs * g[e] + bb[e] + ht[(size_t)m * E_ + e];
    }
}

// ---------------- launch ----------------
extern "C" void kernel_launch(void* const* d_in, const int* in_sizes, int n_in,
                              void* d_out, int out_size)
{
    const float* X    = (const float*)d_in[0];
    const float* amsk = (const float*)d_in[1];
    const float* TE   = (const float*)d_in[2];
    const float* tp   = (const float*)d_in[3];
    const float* Wq   = (const float*)d_in[4];
    const float* bq   = (const float*)d_in[5];
    const float* Wk   = (const float*)d_in[6];
    const float* bk   = (const float*)d_in[7];
    const float* Wv   = (const float*)d_in[8];
    const float* bv   = (const float*)d_in[9];
    const float* Wo   = (const float*)d_in[10];
    const float* bo   = (const float*)d_in[11];
    const float* lng  = (const float*)d_in[12];
    const float* lnb  = (const float*)d_in[13];

    float* out    = (float*)d_out;
    float* scores = out + (size_t)MROWS * E_;

    bf16 *pXhi, *pXlo, *patthi, *pattlo, *phthi, *phtlo, *pctxhi, *pctxlo;
    bf16 *pqhi, *pqlo, *pkhi, *pklo, *pvhi, *pvlo;
    bf16 *pWq1, *pWq2, *pWk1, *pWk2, *pWv1, *pWv2, *pWo1, *pWo2;
    bf16 *pTE1, *pTE2, *pTEt1, *pTEt2;
    float *pht, *pz, *pbq2;
    cudaGetSymbolAddress((void**)&pXhi,   g_Xhi);
    cudaGetSymbolAddress((void**)&pXlo,   g_Xlo);
    cudaGetSymbolAddress((void**)&patthi, g_atthi);
    cudaGetSymbolAddress((void**)&pattlo, g_attlo);
    cudaGetSymbolAddress((void**)&pht,    g_ht);
    cudaGetSymbolAddress((void**)&phthi,  g_hthi);
    cudaGetSymbolAddress((void**)&phtlo,  g_htlo);
    cudaGetSymbolAddress((void**)&pqhi,   g_qhi);
    cudaGetSymbolAddress((void**)&pqlo,   g_qlo);
    cudaGetSymbolAddress((void**)&pkhi,   g_khi);
    cudaGetSymbolAddress((void**)&pklo,   g_klo);
    cudaGetSymbolAddress((void**)&pvhi,   g_vhi);
    cudaGetSymbolAddress((void**)&pvlo,   g_vlo);
    cudaGetSymbolAddress((void**)&pctxhi, g_ctxhi);
    cudaGetSymbolAddress((void**)&pctxlo, g_ctxlo);
    cudaGetSymbolAddress((void**)&pz,     g_z);
    cudaGetSymbolAddress((void**)&pWq1,   g_Wqthi);
    cudaGetSymbolAddress((void**)&pWq2,   g_Wqtlo);
    cudaGetSymbolAddress((void**)&pWk1,   g_Wkthi);
    cudaGetSymbolAddress((void**)&pWk2,   g_Wktlo);
    cudaGetSymbolAddress((void**)&pWv1,   g_Wvthi);
    cudaGetSymbolAddress((void**)&pWv2,   g_Wvtlo);
    cudaGetSymbolAddress((void**)&pWo1,   g_Wothi);
    cudaGetSymbolAddress((void**)&pWo2,   g_Wotlo);
    cudaGetSymbolAddress((void**)&pTE1,   g_TEhi);
    cudaGetSymbolAddress((void**)&pTE2,   g_TElo);
    cudaGetSymbolAddress((void**)&pTEt1,  g_TEthi);
    cudaGetSymbolAddress((void**)&pTEt2,  g_TEtlo);
    cudaGetSymbolAddress((void**)&pbq2,   g_bq2);

    const int gsm = 2 * 4 * 128 * AST * (int)sizeof(bf16);   // 81920
    cudaFuncSetAttribute(mma_gemm<0>, cudaFuncAttributeMaxDynamicSharedMemorySize, gsm);
    cudaFuncSetAttribute(mma_gemm<1>, cudaFuncAttributeMaxDynamicSharedMemorySize, gsm);
    cudaFuncSetAttribute(mma_gemm<2>, cudaFuncAttributeMaxDynamicSharedMemorySize, gsm);
    cudaFuncSetAttribute(mma_gemm<3>, cudaFuncAttributeMaxDynamicSharedMemorySize, gsm);
    cudaFuncSetAttribute(mma_gemm<4>, cudaFuncAttributeMaxDynamicSharedMemorySize, gsm);
    cudaFuncSetAttribute(mma_gemm<5>, cudaFuncAttributeMaxDynamicSharedMemorySize, gsm);
    const int fsm_bytes = 55296 * (int)sizeof(bf16) + 512 * (int)sizeof(float); // 112640
    cudaFuncSetAttribute(flash_mma, cudaFuncAttributeMaxDynamicSharedMemorySize,
                         fsm_bytes);

    dim3 blk(256);

    // ---- prep ----
    split_kernel<<<(MROWS * E_ + 255) / 256, blk>>>(X, pXhi, pXlo, MROWS * E_);
    {
        dim3 tg(24, 24), tb(32, 8);
        transW_kernel<<<tg, tb>>>(Wq, pWq1, pWq2);
        transW_kernel<<<tg, tb>>>(Wk, pWk1, pWk2);
        transW_kernel<<<tg, tb>>>(Wv, pWv1, pWv2);
        transW_kernel<<<tg, tb>>>(Wo, pWo1, pWo2);
    }
    tePad_kernel<<<(128 * E_ + 255) / 256, blk>>>(TE, pTE1, pTE2);
    teT_kernel<<<(E_ * 128 + 255) / 256, blk>>>(TE, pTEt1, pTEt2);
    biasq_kernel<<<3, blk>>>(tp, Wq, bq, pbq2);

    // ---- 1) scores = X @ TE^T ----
    mma_gemm<0><<<dim3(1, 64), blk, gsm>>>(pXhi, pXlo, E_, pTE1, pTE2, E_, E_,
                                           nullptr, nullptr, nullptr, 1.f,
                                           scores, nullptr, nullptr);
    // ---- 2) att = softmax(scores), bf16 split padded ----
    softmax100_kernel<<<MROWS / 8, blk>>>(scores, patthi, pattlo);
    // ---- 3) h_truth = att @ TE + X (fp32 + bf16 split) ----
    mma_gemm<2><<<dim3(6, 64), blk, gsm>>>(patthi, pattlo, 128, pTEt1, pTEt2, 128, 128,
                                           nullptr, X, nullptr, 1.f,
                                           pht, phthi, phtlo);
    // ---- 4) q = (X @ Wq + bq + tp@Wq) * 0.125, split [b,h,t,d] ----
    mma_gemm<4><<<dim3(6, 64), blk, gsm>>>(pXhi, pXlo, E_, pWq1, pWq2, E_, E_,
                                           pbq2, nullptr, nullptr, 0.125f,
                                           nullptr, pqhi, pqlo);
    // ---- 5) k, v ----
    mma_gemm<4><<<dim3(6, 64), blk, gsm>>>(phthi, phtlo, E_, pWk1, pWk2, E_, E_,
                                           bk, nullptr, nullptr, 1.f,
                                           nullptr, pkhi, pklo);
    mma_gemm<5><<<dim3(6, 64), blk, gsm>>>(phthi, phtlo, E_, pWv1, pWv2, E_, E_,
                                           bv, nullptr, nullptr, 1.f,
                                           nullptr, pvhi, pvlo);
    // ---- 6) flash attention (tensor cores, LDSM) ----
    flash_mma<<<dim3(4, H_, B_), blk, fsm_bytes>>>(pqhi, pqlo, pkhi, pklo,
                                                   pvhi, pvlo, amsk,
                                                   pctxhi, pctxlo);
    // ---- 7) z = ctx @ Wo + bo + X + tp ----
    mma_gemm<3><<<dim3(6, 64), blk, gsm>>>(pctxhi, pctxlo, E_, pWo1, pWo2, E_, E_,
                                           bo, X, tp, 1.f,
                                           pz, nullptr, nullptr);
    // ---- 8) out = LN(z) + h_truth ----
    ln_kernel<<<MROWS, blk>>>(pz, lng, lnb, pht, out);
}